// round 12
// baseline (speedup 1.0000x reference)
#include <cuda_runtime.h>
#include <cuda_fp16.h>
#include <cstdint>
#include <math.h>

#define BATCH  32
#define SEQ    1024
#define EMB    200
#define NSTACK 6
#define NHEAD  8
#define MROWS  (BATCH * SEQ)          // 32768
#define KP     224                    // padded K (=7*32)
#define NP     256                    // padded B-operand row count
#define NE     (SEQ * EMB)
#define LNCH   16
#define CHUNK  (NE / LNCH)

// ================= scratch (device globals; zero-initialized) ===============
__device__ float  g_h [MROWS * EMB];
__device__ float  g_q [MROWS * EMB];
__device__ float  g_y [MROWS * EMB];
__device__ float  g_S [BATCH * SEQ * SEQ];
__device__ float  g_wfe[EMB * EMB];
__device__ int    g_off[BATCH];
__device__ double g_ps [BATCH * LNCH];
__device__ double g_ps2[BATCH * LNCH];
// fp16 operand buffers. Pad columns [EMB,KP) never written -> stay 0.
__device__ __half g_Ah [MROWS * KP],  g_Al [MROWS * KP];   // h split (A-side)
__device__ __half g_Ch [MROWS * KP],  g_Cl [MROWS * KP];   // c / relu split
__device__ __half g_Qh [MROWS * KP],  g_Ql [MROWS * KP];   // q split (A); Qh doubles as B
__device__ __half g_QT [BATCH * NP * SEQ];                 // q^T single (B for ctx)
__device__ __half g_Ph [BATCH * SEQ * SEQ], g_Pl [BATCH * SEQ * SEQ];
__device__ __half g_Wq [NP * KP], g_Wf [NP * KP];
__device__ __half g_W1 [NP * KP], g_W2 [NP * KP];

// ================= base-ISA asm helpers =====================================
__device__ __forceinline__ uint32_t smem_u32(const void* p) {
    uint32_t a;
    asm("{ .reg .u64 t; cvta.to.shared.u64 t, %1; cvt.u32.u64 %0, t; }" : "=r"(a) : "l"(p));
    return a;
}
__device__ __forceinline__ void ldsm_x4(uint32_t* r, uint32_t addr) {
    asm volatile("ldmatrix.sync.aligned.m8n8.x4.shared.b16 {%0,%1,%2,%3}, [%4];"
        : "=r"(r[0]), "=r"(r[1]), "=r"(r[2]), "=r"(r[3]) : "r"(addr));
}
__device__ __forceinline__ void mma16816(float* c, const uint32_t* a,
                                         uint32_t b0, uint32_t b1) {
    asm volatile("mma.sync.aligned.m16n8k16.row.col.f32.f16.f16.f32 "
        "{%0,%1,%2,%3}, {%4,%5,%6,%7}, {%8,%9}, {%0,%1,%2,%3};"
        : "+f"(c[0]), "+f"(c[1]), "+f"(c[2]), "+f"(c[3])
        : "r"(a[0]), "r"(a[1]), "r"(a[2]), "r"(a[3]), "r"(b0), "r"(b1));
}
__device__ __forceinline__ void cp16(uint32_t s, const void* g) {
    asm volatile("cp.async.cg.shared.global [%0], [%1], 16;" :: "r"(s), "l"(g));
}
#define CP_COMMIT() asm volatile("cp.async.commit_group;" ::: "memory")

__device__ __forceinline__ void split_store(float v, __half* oh, __half* ol, size_t i) {
    __half hh = __float2half(v);
    oh[i] = hh;
    ol[i] = __float2half(v - __half2float(hh));
}

// ================= prologue kernels =========================================
__global__ void count_zeros_k(const int* __restrict__ x) {
    int b = blockIdx.x;
    __shared__ int cnt;
    if (threadIdx.x == 0) cnt = 0;
    __syncthreads();
    int c = 0;
    for (int i = threadIdx.x; i < SEQ; i += blockDim.x) c += (x[b * SEQ + i] == 0);
    atomicAdd(&cnt, c);
    __syncthreads();
    if (threadIdx.x == 0) g_off[b] = cnt;
}

__global__ void embed_pos_k(const int* __restrict__ x, const float* __restrict__ embed) {
    int row = blockIdx.x;
    int b = row >> 10, l = row & 1023;
    int j = l - g_off[b];
    bool valid = (j >= 0);
    float sv = 0.f, cv = 0.f;
    if (valid) {
        double jf  = (double)j;
        double ang = jf / pow(1000.0, jf / (double)EMB);
        sv = (float)sin(ang); cv = (float)cos(ang);
    }
    int tok = x[row];
    const float* er = embed + (size_t)tok * EMB;
    float*       hr = g_h   + (size_t)row * EMB;
    for (int k = threadIdx.x; k < EMB; k += blockDim.x) {
        float p = valid ? ((k & 1) ? sv : cv) : 0.f;
        float v = er[k] + p;
        hr[k] = v;
        split_store(v, g_Ah, g_Al, (size_t)row * KP + k);
    }
}

__global__ void build_wfe_k(const float* __restrict__ w_fuse) {
    int i = blockIdx.x * blockDim.x + threadIdx.x;
    if (i >= EMB * EMB) return;
    int d = i / EMB, n = i % EMB;
    float s = 0.f;
    for (int h = 0; h < NHEAD; h++) s += w_fuse[(size_t)(h * EMB + d) * EMB + n];
    g_wfe[i] = s;
}

// weight [EMB,EMB] -> transposed single fp16 [NP,KP]: out[n][k] = w[k][n]
__global__ void __launch_bounds__(256) wtsplit_k(const float* __restrict__ w,
                                                 __half* __restrict__ o) {
    int i = blockIdx.x * 256 + threadIdx.x;
    int n = i / KP, k = i % KP;
    float v = (n < EMB && k < EMB) ? w[k * EMB + n] : 0.f;
    o[i] = __float2half(v);
}

// q [B*SEQ, EMB] -> per-batch transposed single fp16 [B][NP][SEQ]
__global__ void tqsplit_k(const float* __restrict__ q, __half* __restrict__ o) {
    __shared__ float t[32][33];
    int b = blockIdx.z;
    int k0 = blockIdx.x * 32, n0 = blockIdx.y * 32;
    int tx = threadIdx.x, ty = threadIdx.y;   // (32, 8)
#pragma unroll
    for (int j = 0; j < 4; j++) {
        int k = k0 + ty + j * 8, n = n0 + tx;
        t[ty + j * 8][tx] = (n < EMB) ? q[((size_t)b * SEQ + k) * EMB + n] : 0.f;
    }
    __syncthreads();
#pragma unroll
    for (int j = 0; j < 4; j++) {
        int n = n0 + ty + j * 8, k = k0 + tx;
        o[(size_t)b * NP * SEQ + (size_t)n * SEQ + k] = __float2half(t[tx][ty + j * 8]);
    }
}

// ================= shared tiling constants ==================================
#define RS 40                          // smem row stride in halfs (80B)
#define STG_A (128 * RS * 2)           // 10240 B per 128-row array per stage
#define STG_B256 (256 * RS * 2)        // 20480 B per 256-row array per stage

// ================= tgemm128: 128x128 symmetric score GEMM ===================
// S = alpha * (Ah+Al) @ Bs^T, upper-tri tile map + mirror via smem transpose.
#define SM_TOT128 69632

__global__ void __launch_bounds__(256, 2)
tgemm128_score(const __half* __restrict__ Ah, const __half* __restrict__ Al,
               const __half* __restrict__ Bs, float* __restrict__ C,
               int K, float alpha, size_t sA, size_t sC)
{
    extern __shared__ __align__(16) char dsm[];
    const uint32_t base = smem_u32(dsm);
    const uint32_t uAh = base;
    const uint32_t uAl = base + 2 * STG_A;
    const uint32_t uBs = base + 4 * STG_A;

    const int tid = threadIdx.x, wid = tid >> 5, lane = tid & 31;
    int t = blockIdx.x, ti = 0;
    while (t >= 8 - ti) { t -= 8 - ti; ti++; }
    const int tj = ti + t;
    const int m0 = ti * 128, n0 = tj * 128;
    const int bz = blockIdx.z;
    Ah += (size_t)bz * sA;  Al += (size_t)bz * sA;
    Bs += (size_t)bz * sA;
    C  += (size_t)bz * sC;

    const int wm = wid & 3, wn = wid >> 2;
    const int mb = wm * 32, nb = wn * 64;

    const uint32_t aRow = (lane & 15);
    const uint32_t aCol = (lane >> 4) * 16;
    const uint32_t bRow = (lane & 7) + ((lane >> 4) << 3);
    const uint32_t bCol = ((lane >> 3) & 1) * 16;

    const int fr0 = tid >> 2, fc0 = (tid & 3);
    const int fr1 = fr0 + 64;
    const uint32_t so0 = fr0 * (RS * 2) + fc0 * 16;
    const uint32_t so1 = fr1 * (RS * 2) + fc0 * 16;

    float acc[2][8][4];
#pragma unroll
    for (int f = 0; f < 2; f++)
#pragma unroll
        for (int j = 0; j < 8; j++)
#pragma unroll
            for (int e = 0; e < 4; e++) acc[f][j][e] = 0.f;

#define ISSUE128(ck, st) do { \
    uint32_t o = (uint32_t)(st) * STG_A; \
    size_t kk = (size_t)(ck) * 32 + fc0 * 8; \
    size_t ga0 = (size_t)(m0 + fr0) * K + kk; \
    size_t ga1 = (size_t)(m0 + fr1) * K + kk; \
    size_t gb0 = (size_t)(n0 + fr0) * K + kk; \
    size_t gb1 = (size_t)(n0 + fr1) * K + kk; \
    cp16(uAh + o + so0, Ah + ga0); cp16(uAh + o + so1, Ah + ga1); \
    cp16(uAl + o + so0, Al + ga0); cp16(uAl + o + so1, Al + ga1); \
    cp16(uBs + o + so0, Bs + gb0); cp16(uBs + o + so1, Bs + gb1); \
    CP_COMMIT(); \
} while (0)

    const int nck = K >> 5;
    ISSUE128(0, 0);
    for (int ck = 0; ck < nck; ck++) {
        const int st = ck & 1;
        if (ck + 1 < nck) {
            ISSUE128(ck + 1, (ck + 1) & 1);
            asm volatile("cp.async.wait_group 1;" ::: "memory");
        } else {
            asm volatile("cp.async.wait_group 0;" ::: "memory");
        }
        __syncthreads();

        const uint32_t oAh = uAh + st * STG_A;
        const uint32_t oAl = uAl + st * STG_A;
        const uint32_t oBs = uBs + st * STG_A;
#pragma unroll
        for (int kh = 0; kh < 2; kh++) {
            const uint32_t kb = kh * 32;
            uint32_t ah[2][4], al[2][4];
            ldsm_x4(ah[0], oAh + (mb + aRow)      * (RS * 2) + kb + aCol);
            ldsm_x4(ah[1], oAh + (mb + 16 + aRow) * (RS * 2) + kb + aCol);
            ldsm_x4(al[0], oAl + (mb + aRow)      * (RS * 2) + kb + aCol);
            ldsm_x4(al[1], oAl + (mb + 16 + aRow) * (RS * 2) + kb + aCol);
#pragma unroll
            for (int g = 0; g < 4; g++) {
                uint32_t bh[4];
                ldsm_x4(bh, oBs + (nb + g * 16 + bRow) * (RS * 2) + kb + bCol);
#pragma unroll
                for (int f = 0; f < 2; f++) {
#pragma unroll
                    for (int nn = 0; nn < 2; nn++) {
                        float* cc = acc[f][g * 2 + nn];
                        mma16816(cc, ah[f], bh[2 * nn], bh[2 * nn + 1]);
                        mma16816(cc, al[f], bh[2 * nn], bh[2 * nn + 1]);
                    }
                }
            }
        }
        __syncthreads();
    }

    const int tg = lane >> 2, tig = lane & 3;
    float* ts = (float*)dsm;               // 128x132 transpose buffer
#pragma unroll
    for (int f = 0; f < 2; f++) {
        int rl0 = mb + f * 16 + tg;
        float* c0 = C + (size_t)(m0 + rl0) * SEQ;
        float* c1 = C + (size_t)(m0 + rl0 + 8) * SEQ;
#pragma unroll
        for (int j = 0; j < 8; j++) {
            float* a = acc[f][j];
#pragma unroll
            for (int e = 0; e < 2; e++) {
                int cl = nb + j * 8 + tig * 2 + e;
                float v0 = a[e] * alpha, v1 = a[e + 2] * alpha;
                c0[n0 + cl] = v0;
                c1[n0 + cl] = v1;
                ts[cl * 132 + rl0]     = v0;
                ts[cl * 132 + rl0 + 8] = v1;
            }
        }
    }
    __syncthreads();
    if (ti != tj) {
        for (int tt = tid; tt < 128 * 32; tt += 256) {
            int nl = tt >> 5, c4 = (tt & 31) * 4;
            float4 v = *(const float4*)&ts[nl * 132 + c4];
            *(float4*)&C[(size_t)(n0 + nl) * SEQ + m0 + c4] = v;
        }
    }
}

// ================= tgemm256: 128x256 full-N tile, 512 threads ===============
// C tile [128,256] = alpha*((Ah+Al) @ B^T) (+bias)(+relu)(+resid)(+split out)
// B has exactly NP=256 rows (weights / q^T). A loaded ONCE per M-tile.
#define SM_TOT256 (4 * STG_A + 2 * STG_B256)   // 81920

__global__ void __launch_bounds__(512, 1)
tgemm256(const __half* __restrict__ Ah, const __half* __restrict__ Al,
         const __half* __restrict__ Bs,
         float* __restrict__ C, const float* __restrict__ bias,
         const float* __restrict__ resid,
         __half* __restrict__ spH, __half* __restrict__ spL,
         int K, int Nout, float alpha, int do_relu,
         size_t sA, size_t sB, size_t sC, size_t sSp)
{
    extern __shared__ __align__(16) char dsm[];
    const uint32_t base = smem_u32(dsm);
    const uint32_t uAh = base;
    const uint32_t uAl = base + 2 * STG_A;
    const uint32_t uBs = base + 4 * STG_A;

    const int tid = threadIdx.x, wid = tid >> 5, lane = tid & 31;
    const int m0 = blockIdx.y * 128;
    const int bz = blockIdx.z;
    Ah += (size_t)bz * sA;  Al += (size_t)bz * sA;
    Bs += (size_t)bz * sB;
    if (C) C += (size_t)bz * sC;
    if (resid) resid += (size_t)bz * sC;

    const int wm = wid & 3, wn = wid >> 2;        // 4m x 4n warps
    const int mb = wm * 32, nb = wn * 64;

    const uint32_t aRow = (lane & 15);
    const uint32_t aCol = (lane >> 4) * 16;
    const uint32_t bRow = (lane & 7) + ((lane >> 4) << 3);
    const uint32_t bCol = ((lane >> 3) & 1) * 16;

    const int fr = tid >> 2, fc0 = (tid & 3);     // 128 rows, 4 thr/row
    const uint32_t so0 = fr * (RS * 2) + fc0 * 16;

    float acc[2][8][4];
#pragma unroll
    for (int f = 0; f < 2; f++)
#pragma unroll
        for (int j = 0; j < 8; j++)
#pragma unroll
            for (int e = 0; e < 4; e++) acc[f][j][e] = 0.f;

#define ISSUE256(ck, st) do { \
    uint32_t oA = (uint32_t)(st) * STG_A; \
    uint32_t oB = (uint32_t)(st) * STG_B256; \
    size_t kk = (size_t)(ck) * 32 + fc0 * 8; \
    size_t ga = (size_t)(m0 + fr) * K + kk; \
    size_t gb0 = (size_t)fr * K + kk; \
    size_t gb1 = (size_t)(fr + 128) * K + kk; \
    cp16(uAh + oA + so0, Ah + ga); \
    cp16(uAl + oA + so0, Al + ga); \
    cp16(uBs + oB + so0, Bs + gb0); \
    cp16(uBs + oB + so0 + 128 * RS * 2, Bs + gb1); \
    CP_COMMIT(); \
} while (0)

    const int nck = K >> 5;
    ISSUE256(0, 0);
    for (int ck = 0; ck < nck; ck++) {
        const int st = ck & 1;
        if (ck + 1 < nck) {
            ISSUE256(ck + 1, (ck + 1) & 1);
            asm volatile("cp.async.wait_group 1;" ::: "memory");
        } else {
            asm volatile("cp.async.wait_group 0;" ::: "memory");
        }
        __syncthreads();

        const uint32_t oAh = uAh + st * STG_A;
        const uint32_t oAl = uAl + st * STG_A;
        const uint32_t oBs = uBs + st * STG_B256;
#pragma unroll
        for (int kh = 0; kh < 2; kh++) {
            const uint32_t kb = kh * 32;
            uint32_t ah[2][4], al[2][4];
            ldsm_x4(ah[0], oAh + (mb + aRow)      * (RS * 2) + kb + aCol);
            ldsm_x4(ah[1], oAh + (mb + 16 + aRow) * (RS * 2) + kb + aCol);
            ldsm_x4(al[0], oAl + (mb + aRow)      * (RS * 2) + kb + aCol);
            ldsm_x4(al[1], oAl + (mb + 16 + aRow) * (RS * 2) + kb + aCol);
#pragma unroll
            for (int g = 0; g < 4; g++) {
                uint32_t bh[4];
                ldsm_x4(bh, oBs + (nb + g * 16 + bRow) * (RS * 2) + kb + bCol);
#pragma unroll
                for (int f = 0; f < 2; f++) {
#pragma unroll
                    for (int nn = 0; nn < 2; nn++) {
                        float* cc = acc[f][g * 2 + nn];
                        mma16816(cc, ah[f], bh[2 * nn], bh[2 * nn + 1]);
                        mma16816(cc, al[f], bh[2 * nn], bh[2 * nn + 1]);
                    }
                }
            }
        }
        __syncthreads();
    }

    const int tg = lane >> 2, tig = lane & 3;
#pragma unroll
    for (int f = 0; f < 2; f++) {
        int r0 = m0 + mb + f * 16 + tg;
        float* c0 = C ? C + (size_t)r0 * Nout : nullptr;
        float* c1 = C ? C + (size_t)(r0 + 8) * Nout : nullptr;
        const float* rr0 = resid ? resid + (size_t)r0 * Nout : nullptr;
        const float* rr1 = resid ? resid + (size_t)(r0 + 8) * Nout : nullptr;
        __half* sh0 = spH ? spH + (size_t)bz * sSp + (size_t)r0 * KP : nullptr;
        __half* sh1 = spH ? spH + (size_t)bz * sSp + (size_t)(r0 + 8) * KP : nullptr;
        __half* sl0 = spL ? spL + (size_t)bz * sSp + (size_t)r0 * KP : nullptr;
        __half* sl1 = spL ? spL + (size_t)bz * sSp + (size_t)(r0 + 8) * KP : nullptr;
#pragma unroll
        for (int j = 0; j < 8; j++) {
            int cb = nb + j * 8 + tig * 2;
            float* a = acc[f][j];
#pragma unroll
            for (int e = 0; e < 2; e++) {
                int col = cb + e;
                if (col < Nout) {
                    float v0 = a[e] * alpha, v1 = a[e + 2] * alpha;
                    if (bias) { v0 += bias[col]; v1 += bias[col]; }
                    if (do_relu) { v0 = fmaxf(v0, 0.f); v1 = fmaxf(v1, 0.f); }
                    if (rr0) { v0 += rr0[col]; v1 += rr1[col]; }
                    if (c0) { c0[col] = v0; c1[col] = v1; }
                    if (sh0) {
                        split_store(v0, sh0, sl0, (size_t)col);
                        split_store(v1, sh1, sl1, (size_t)col);
                    }
                }
            }
        }
    }
}

// ================= softmax: fp32 scores -> fp16-split probabilities =========
__global__ void __launch_bounds__(256) softmax_rows_k(const float* __restrict__ S,
                                                      __half* __restrict__ Ph,
                                                      __half* __restrict__ Pl) {
    size_t row = blockIdx.x;
    const float* rp = S + row * SEQ;
    int t = threadIdx.x;
    float4 v = ((const float4*)rp)[t];
    float m = fmaxf(fmaxf(v.x, v.y), fmaxf(v.z, v.w));
#pragma unroll
    for (int o = 16; o; o >>= 1) m = fmaxf(m, __shfl_xor_sync(0xffffffffu, m, o));
    __shared__ float red[8], red2[8];
    if ((t & 31) == 0) red[t >> 5] = m;
    __syncthreads();
    m = red[0];
#pragma unroll
    for (int i = 1; i < 8; i++) m = fmaxf(m, red[i]);
    v.x = __expf(v.x - m); v.y = __expf(v.y - m);
    v.z = __expf(v.z - m); v.w = __expf(v.w - m);
    float s = v.x + v.y + v.z + v.w;
#pragma unroll
    for (int o = 16; o; o >>= 1) s += __shfl_xor_sync(0xffffffffu, s, o);
    if ((t & 31) == 0) red2[t >> 5] = s;
    __syncthreads();
    s = 0.f;
#pragma unroll
    for (int i = 0; i < 8; i++) s += red2[i];
    float inv = 1.0f / s;
    float p0 = v.x * inv, p1 = v.y * inv, p2 = v.z * inv, p3 = v.w * inv;
    __half h0 = __float2half(p0), h1 = __float2half(p1);
    __half h2 = __float2half(p2), h3 = __float2half(p3);
    size_t o2 = (row * SEQ) / 2 + 2 * t;
    ((__half2*)Ph)[o2]     = __halves2half2(h0, h1);
    ((__half2*)Ph)[o2 + 1] = __halves2half2(h2, h3);
    ((__half2*)Pl)[o2]     = __halves2half2(__float2half(p0 - __half2float(h0)),
                                            __float2half(p1 - __half2float(h1)));
    ((__half2*)Pl)[o2 + 1] = __halves2half2(__float2half(p2 - __half2float(h2)),
                                            __float2half(p3 - __half2float(h3)));
}

// ================= layernorm (two-pass over [SEQ,EMB] per batch) ============
__global__ void __launch_bounds__(256) ln2_pass1(const float* __restrict__ y) {
    int b = blockIdx.x, ch = blockIdx.y;
    const float* p = y + (size_t)b * NE + (size_t)ch * CHUNK;
    int t = threadIdx.x;
    double s = 0.0, s2 = 0.0;
    for (int i = t; i < CHUNK; i += 256) {
        float v = p[i];
        s += (double)v; s2 += (double)v * (double)v;
    }
#pragma unroll
    for (int o = 16; o; o >>= 1) {
        s  += __shfl_xor_sync(0xffffffffu, s,  o);
        s2 += __shfl_xor_sync(0xffffffffu, s2, o);
    }
    __shared__ double rs[8], rs2[8];
    if ((t & 31) == 0) { rs[t >> 5] = s; rs2[t >> 5] = s2; }
    __syncthreads();
    if (t == 0) {
        double S = 0.0, S2 = 0.0;
        for (int i = 0; i < 8; i++) { S += rs[i]; S2 += rs2[i]; }
        g_ps [b * LNCH + ch] = S;
        g_ps2[b * LNCH + ch] = S2;
    }
}

__global__ void __launch_bounds__(256) ln2_pass2(const float* __restrict__ y,
                                                 float* __restrict__ out,
                                                 __half* __restrict__ oh,
                                                 __half* __restrict__ ol) {
    int b = blockIdx.x, ch = blockIdx.y;
    double S = 0.0, S2 = 0.0;
    for (int i = 0; i < LNCH; i++) { S += g_ps[b * LNCH + i]; S2 += g_ps2[b * LNCH + i]; }
    const double n = (double)NE;
    double mu = S / n, var = S2 / n - mu * mu;
    float muf = (float)mu;
    float inv = (float)(1.0 / sqrt(var + 1e-5));
    size_t base = (size_t)b * NE + (size_t)ch * CHUNK;
    for (int i = threadIdx.x; i < CHUNK; i += 256) {
        size_t e = base + i;
        float v = (y[e] - muf) * inv;
        out[e] = v;
        if (oh) {
            size_t r = e / EMB;
            int    k = (int)(e - r * EMB);
            split_store(v, oh, ol, r * KP + k);
        }
    }
}

// ================= host orchestration =======================================
extern "C" void kernel_launch(void* const* d_in, const int* in_sizes, int n_in,
                              void* d_out, int out_size)
{
    const int*   x      = (const int*)  d_in[0];
    const float* embed  = (const float*)d_in[1];
    const float* w_qkv  = (const float*)d_in[2];
    const float* b_qkv  = (const float*)d_in[3];
    const float* w_fuse = (const float*)d_in[4];
    const float* b_fuse = (const float*)d_in[5];
    const float* w1     = (const float*)d_in[6];
    const float* b1     = (const float*)d_in[7];
    const float* w2     = (const float*)d_in[8];
    const float* b2     = (const float*)d_in[9];
    float*       out    = (float*)d_out;
    (void)in_sizes; (void)n_in; (void)out_size;

    cudaFuncSetAttribute(tgemm128_score, cudaFuncAttributeMaxDynamicSharedMemorySize, SM_TOT128);
    cudaFuncSetAttribute(tgemm256, cudaFuncAttributeMaxDynamicSharedMemorySize, SM_TOT256);

    float *h, *q, *y, *S, *wfe;
    cudaGetSymbolAddress((void**)&h,   g_h);
    cudaGetSymbolAddress((void**)&q,   g_q);
    cudaGetSymbolAddress((void**)&y,   g_y);
    cudaGetSymbolAddress((void**)&S,   g_S);
    cudaGetSymbolAddress((void**)&wfe, g_wfe);
    __half *Ahp,*Alp,*Chp,*Clp,*Qhp,*Qlp,*QTp,*Php,*Plp,*Wq,*Wf,*W1,*W2;
    cudaGetSymbolAddress((void**)&Ahp, g_Ah);  cudaGetSymbolAddress((void**)&Alp, g_Al);
    cudaGetSymbolAddress((void**)&Chp, g_Ch);  cudaGetSymbolAddress((void**)&Clp, g_Cl);
    cudaGetSymbolAddress((void**)&Qhp, g_Qh);  cudaGetSymbolAddress((void**)&Qlp, g_Ql);
    cudaGetSymbolAddress((void**)&QTp, g_QT);
    cudaGetSymbolAddress((void**)&Php, g_Ph);  cudaGetSymbolAddress((void**)&Plp, g_Pl);
    cudaGetSymbolAddress((void**)&Wq,  g_Wq);  cudaGetSymbolAddress((void**)&Wf,  g_Wf);
    cudaGetSymbolAddress((void**)&W1,  g_W1);  cudaGetSymbolAddress((void**)&W2,  g_W2);

    const float inv_scale = 1.0f / sqrtf(200.0f);

    dim3 gFull(1, MROWS / 128, 1);       // 256 blocks, full-N tiles
    dim3 gScoreSym(36, 1, BATCH);
    dim3 gCtx(1, SEQ / 128, BATCH);      // 256 blocks
    dim3 gTq(SEQ / 32, NP / 32, BATCH);
    dim3 bTq(32, 8);
    dim3 gLN(BATCH, LNCH);
    const size_t sQK = (size_t)SEQ * KP;
    const size_t sSS = (size_t)SEQ * SEQ;
    const size_t sQT = (size_t)NP * SEQ;

    // launch order keeps capture slot (4th launch) = tgemm256 (q-projection)
    count_zeros_k<<<BATCH, 256>>>(x);                                   // 1
    embed_pos_k  <<<MROWS, 256>>>(x, embed);                            // 2
    wtsplit_k<<<(NP * KP) / 256, 256>>>(w_qkv, Wq);                     // 3

    for (int s = 0; s < NSTACK; s++) {
        // q = h @ w_qkv + b_qkv  (fp32 q + fp16 hi/lo split)
        tgemm256<<<gFull, 512, SM_TOT256>>>(Ahp, Alp, Wq, q, b_qkv, nullptr,
                                            Qhp, Qlp, KP, EMB, 1.f, 0, 0, 0, 0, 0);  // 4
        tqsplit_k<<<gTq, bTq>>>(q, QTp);
        // S = q q^T / sqrt(D): symmetric 36 upper tiles + mirror
        tgemm128_score<<<gScoreSym, 256, SM_TOT128>>>(Qhp, Qlp, Qhp, S,
                                                      KP, inv_scale, sQK, sSS);
        softmax_rows_k<<<MROWS, 256>>>(S, Php, Plp);
        if (s == 0) {
            build_wfe_k<<<(EMB * EMB + 255) / 256, 256>>>(w_fuse);
            wtsplit_k<<<(NP * KP) / 256, 256>>>(wfe, Wf);
            wtsplit_k<<<(NP * KP) / 256, 256>>>(w1,  W1);
            wtsplit_k<<<(NP * KP) / 256, 256>>>(w2,  W2);
        }
        // c = P @ q   (A = P split, B = q^T single; split-only output)
        tgemm256<<<gCtx, 512, SM_TOT256>>>(Php, Plp, QTp, nullptr, nullptr, nullptr,
                                           Chp, Clp, SEQ, EMB, 1.f, 0, sSS, sQT, 0, sQK);
        // y = c @ wfe + b_fuse + h
        tgemm256<<<gFull, 512, SM_TOT256>>>(Chp, Clp, Wf, y, b_fuse, h,
                                            nullptr, nullptr, KP, EMB, 1.f, 0, 0, 0, 0, 0);
        ln2_pass1<<<gLN, 256>>>(y);
        ln2_pass2<<<gLN, 256>>>(y, h, Ahp, Alp);
        // ffn: t = relu(h@w1+b1) (split-only) ; y = t@w2+b2+h
        tgemm256<<<gFull, 512, SM_TOT256>>>(Ahp, Alp, W1, nullptr, b1, nullptr,
                                            Chp, Clp, KP, EMB, 1.f, 1, 0, 0, 0, 0);
        tgemm256<<<gFull, 512, SM_TOT256>>>(Chp, Clp, W2, y, b2, h,
                                            nullptr, nullptr, KP, EMB, 1.f, 0, 0, 0, 0, 0);
        ln2_pass1<<<gLN, 256>>>(y);
        if (s == NSTACK - 1)
            ln2_pass2<<<gLN, 256>>>(y, out, nullptr, nullptr);
        else
            ln2_pass2<<<gLN, 256>>>(y, h, Ahp, Alp);
    }
}

// round 13
// speedup vs baseline: 1.0624x; 1.0624x over previous
#include <cuda_runtime.h>
#include <cuda_fp16.h>
#include <cstdint>
#include <math.h>

#define BATCH  32
#define SEQ    1024
#define EMB    200
#define NSTACK 6
#define NHEAD  8
#define MROWS  (BATCH * SEQ)          // 32768
#define KP     224                    // padded K (=7*32)
#define NP     256                    // padded B-operand row count
#define NE     (SEQ * EMB)
#define LNCH   16
#define CHUNK  (NE / LNCH)

// ================= scratch (device globals; zero-initialized) ===============
__device__ float  g_h [MROWS * EMB];
__device__ float  g_q [MROWS * EMB];
__device__ float  g_y [MROWS * EMB];
__device__ float  g_S [BATCH * SEQ * SEQ];
__device__ float  g_wfe[EMB * EMB];
__device__ int    g_off[BATCH];
__device__ double g_ps [BATCH * LNCH];
__device__ double g_ps2[BATCH * LNCH];
// fp16 operand buffers. Pad columns [EMB,KP) never written -> stay 0.
__device__ __half g_Ah [MROWS * KP],  g_Al [MROWS * KP];   // h split (A-side)
__device__ __half g_Ch [MROWS * KP],  g_Cl [MROWS * KP];   // c / relu split
__device__ __half g_Qh [MROWS * KP],  g_Ql [MROWS * KP];   // q split (A); Qh doubles as B
__device__ __half g_QT [BATCH * NP * SEQ];                 // q^T single (B for ctx)
__device__ __half g_Ph [BATCH * SEQ * SEQ];                // softmax probs, single fp16
__device__ __half g_Wq [NP * KP], g_Wf [NP * KP];
__device__ __half g_W1 [NP * KP], g_W2 [NP * KP];

// ================= base-ISA asm helpers =====================================
__device__ __forceinline__ uint32_t smem_u32(const void* p) {
    uint32_t a;
    asm("{ .reg .u64 t; cvta.to.shared.u64 t, %1; cvt.u32.u64 %0, t; }" : "=r"(a) : "l"(p));
    return a;
}
__device__ __forceinline__ void ldsm_x4(uint32_t* r, uint32_t addr) {
    asm volatile("ldmatrix.sync.aligned.m8n8.x4.shared.b16 {%0,%1,%2,%3}, [%4];"
        : "=r"(r[0]), "=r"(r[1]), "=r"(r[2]), "=r"(r[3]) : "r"(addr));
}
__device__ __forceinline__ void mma16816(float* c, const uint32_t* a,
                                         uint32_t b0, uint32_t b1) {
    asm volatile("mma.sync.aligned.m16n8k16.row.col.f32.f16.f16.f32 "
        "{%0,%1,%2,%3}, {%4,%5,%6,%7}, {%8,%9}, {%0,%1,%2,%3};"
        : "+f"(c[0]), "+f"(c[1]), "+f"(c[2]), "+f"(c[3])
        : "r"(a[0]), "r"(a[1]), "r"(a[2]), "r"(a[3]), "r"(b0), "r"(b1));
}
__device__ __forceinline__ void cp16(uint32_t s, const void* g) {
    asm volatile("cp.async.cg.shared.global [%0], [%1], 16;" :: "r"(s), "l"(g));
}
#define CP_COMMIT() asm volatile("cp.async.commit_group;" ::: "memory")

__device__ __forceinline__ void split_store(float v, __half* oh, __half* ol, size_t i) {
    __half hh = __float2half(v);
    oh[i] = hh;
    ol[i] = __float2half(v - __half2float(hh));
}

// ================= prologue kernels =========================================
__global__ void count_zeros_k(const int* __restrict__ x) {
    int b = blockIdx.x;
    __shared__ int cnt;
    if (threadIdx.x == 0) cnt = 0;
    __syncthreads();
    int c = 0;
    for (int i = threadIdx.x; i < SEQ; i += blockDim.x) c += (x[b * SEQ + i] == 0);
    atomicAdd(&cnt, c);
    __syncthreads();
    if (threadIdx.x == 0) g_off[b] = cnt;
}

__global__ void embed_pos_k(const int* __restrict__ x, const float* __restrict__ embed) {
    int row = blockIdx.x;
    int b = row >> 10, l = row & 1023;
    int j = l - g_off[b];
    bool valid = (j >= 0);
    float sv = 0.f, cv = 0.f;
    if (valid) {
        double jf  = (double)j;
        double ang = jf / pow(1000.0, jf / (double)EMB);
        sv = (float)sin(ang); cv = (float)cos(ang);
    }
    int tok = x[row];
    const float* er = embed + (size_t)tok * EMB;
    float*       hr = g_h   + (size_t)row * EMB;
    for (int k = threadIdx.x; k < EMB; k += blockDim.x) {
        float p = valid ? ((k & 1) ? sv : cv) : 0.f;
        float v = er[k] + p;
        hr[k] = v;
        split_store(v, g_Ah, g_Al, (size_t)row * KP + k);
    }
}

__global__ void build_wfe_k(const float* __restrict__ w_fuse) {
    int i = blockIdx.x * blockDim.x + threadIdx.x;
    if (i >= EMB * EMB) return;
    int d = i / EMB, n = i % EMB;
    float s = 0.f;
    for (int h = 0; h < NHEAD; h++) s += w_fuse[(size_t)(h * EMB + d) * EMB + n];
    g_wfe[i] = s;
}

// weight [EMB,EMB] -> transposed single fp16 [NP,KP]: out[n][k] = w[k][n]
__global__ void __launch_bounds__(256) wtsplit_k(const float* __restrict__ w,
                                                 __half* __restrict__ o) {
    int i = blockIdx.x * 256 + threadIdx.x;
    int n = i / KP, k = i % KP;
    float v = (n < EMB && k < EMB) ? w[k * EMB + n] : 0.f;
    o[i] = __float2half(v);
}

// q [B*SEQ, EMB] -> per-batch transposed single fp16 [B][NP][SEQ]
__global__ void tqsplit_k(const float* __restrict__ q, __half* __restrict__ o) {
    __shared__ float t[32][33];
    int b = blockIdx.z;
    int k0 = blockIdx.x * 32, n0 = blockIdx.y * 32;
    int tx = threadIdx.x, ty = threadIdx.y;   // (32, 8)
#pragma unroll
    for (int j = 0; j < 4; j++) {
        int k = k0 + ty + j * 8, n = n0 + tx;
        t[ty + j * 8][tx] = (n < EMB) ? q[((size_t)b * SEQ + k) * EMB + n] : 0.f;
    }
    __syncthreads();
#pragma unroll
    for (int j = 0; j < 4; j++) {
        int n = n0 + ty + j * 8, k = k0 + tx;
        o[(size_t)b * NP * SEQ + (size_t)n * SEQ + k] = __float2half(t[tx][ty + j * 8]);
    }
}

// ================= shared tiling constants ==================================
#define RS 40                          // smem row stride in halfs (80B)
#define STG_A (128 * RS * 2)           // 10240 B per 128-row array per stage
#define STG_B (64 * RS * 2)            // 5120 B per 64-row array per stage

// ================= tgemm128: 128x128 symmetric score GEMM ===================
// S = alpha * (Ah+Al) @ Bs^T, upper-tri tile map + mirror via smem transpose.
#define SM_TOT128 69632

__global__ void __launch_bounds__(256, 2)
tgemm128_score(const __half* __restrict__ Ah, const __half* __restrict__ Al,
               const __half* __restrict__ Bs, float* __restrict__ C,
               int K, float alpha, size_t sA, size_t sC)
{
    extern __shared__ __align__(16) char dsm[];
    const uint32_t base = smem_u32(dsm);
    const uint32_t uAh = base;
    const uint32_t uAl = base + 2 * STG_A;
    const uint32_t uBs = base + 4 * STG_A;

    const int tid = threadIdx.x, wid = tid >> 5, lane = tid & 31;
    int t = blockIdx.x, ti = 0;
    while (t >= 8 - ti) { t -= 8 - ti; ti++; }
    const int tj = ti + t;
    const int m0 = ti * 128, n0 = tj * 128;
    const int bz = blockIdx.z;
    Ah += (size_t)bz * sA;  Al += (size_t)bz * sA;
    Bs += (size_t)bz * sA;
    C  += (size_t)bz * sC;

    const int wm = wid & 3, wn = wid >> 2;
    const int mb = wm * 32, nb = wn * 64;

    const uint32_t aRow = (lane & 15);
    const uint32_t aCol = (lane >> 4) * 16;
    const uint32_t bRow = (lane & 7) + ((lane >> 4) << 3);
    const uint32_t bCol = ((lane >> 3) & 1) * 16;

    const int fr0 = tid >> 2, fc0 = (tid & 3);
    const int fr1 = fr0 + 64;
    const uint32_t so0 = fr0 * (RS * 2) + fc0 * 16;
    const uint32_t so1 = fr1 * (RS * 2) + fc0 * 16;

    float acc[2][8][4];
#pragma unroll
    for (int f = 0; f < 2; f++)
#pragma unroll
        for (int j = 0; j < 8; j++)
#pragma unroll
            for (int e = 0; e < 4; e++) acc[f][j][e] = 0.f;

#define ISSUE128(ck, st) do { \
    uint32_t o = (uint32_t)(st) * STG_A; \
    size_t kk = (size_t)(ck) * 32 + fc0 * 8; \
    size_t ga0 = (size_t)(m0 + fr0) * K + kk; \
    size_t ga1 = (size_t)(m0 + fr1) * K + kk; \
    size_t gb0 = (size_t)(n0 + fr0) * K + kk; \
    size_t gb1 = (size_t)(n0 + fr1) * K + kk; \
    cp16(uAh + o + so0, Ah + ga0); cp16(uAh + o + so1, Ah + ga1); \
    cp16(uAl + o + so0, Al + ga0); cp16(uAl + o + so1, Al + ga1); \
    cp16(uBs + o + so0, Bs + gb0); cp16(uBs + o + so1, Bs + gb1); \
    CP_COMMIT(); \
} while (0)

    const int nck = K >> 5;
    ISSUE128(0, 0);
    for (int ck = 0; ck < nck; ck++) {
        const int st = ck & 1;
        if (ck + 1 < nck) {
            ISSUE128(ck + 1, (ck + 1) & 1);
            asm volatile("cp.async.wait_group 1;" ::: "memory");
        } else {
            asm volatile("cp.async.wait_group 0;" ::: "memory");
        }
        __syncthreads();

        const uint32_t oAh = uAh + st * STG_A;
        const uint32_t oAl = uAl + st * STG_A;
        const uint32_t oBs = uBs + st * STG_A;
#pragma unroll
        for (int kh = 0; kh < 2; kh++) {
            const uint32_t kb = kh * 32;
            uint32_t ah[2][4], al[2][4];
            ldsm_x4(ah[0], oAh + (mb + aRow)      * (RS * 2) + kb + aCol);
            ldsm_x4(ah[1], oAh + (mb + 16 + aRow) * (RS * 2) + kb + aCol);
            ldsm_x4(al[0], oAl + (mb + aRow)      * (RS * 2) + kb + aCol);
            ldsm_x4(al[1], oAl + (mb + 16 + aRow) * (RS * 2) + kb + aCol);
#pragma unroll
            for (int g = 0; g < 4; g++) {
                uint32_t bh[4];
                ldsm_x4(bh, oBs + (nb + g * 16 + bRow) * (RS * 2) + kb + bCol);
#pragma unroll
                for (int f = 0; f < 2; f++) {
#pragma unroll
                    for (int nn = 0; nn < 2; nn++) {
                        float* cc = acc[f][g * 2 + nn];
                        mma16816(cc, ah[f], bh[2 * nn], bh[2 * nn + 1]);
                        mma16816(cc, al[f], bh[2 * nn], bh[2 * nn + 1]);
                    }
                }
            }
        }
        __syncthreads();
    }

    const int tg = lane >> 2, tig = lane & 3;
    float* ts = (float*)dsm;               // 128x132 transpose buffer
#pragma unroll
    for (int f = 0; f < 2; f++) {
        int rl0 = mb + f * 16 + tg;
        float* c0 = C + (size_t)(m0 + rl0) * SEQ;
        float* c1 = C + (size_t)(m0 + rl0 + 8) * SEQ;
#pragma unroll
        for (int j = 0; j < 8; j++) {
            float* a = acc[f][j];
#pragma unroll
            for (int e = 0; e < 2; e++) {
                int cl = nb + j * 8 + tig * 2 + e;
                float v0 = a[e] * alpha, v1 = a[e + 2] * alpha;
                c0[n0 + cl] = v0;
                c1[n0 + cl] = v1;
                ts[cl * 132 + rl0]     = v0;
                ts[cl * 132 + rl0 + 8] = v1;
            }
        }
    }
    __syncthreads();
    if (ti != tj) {
        for (int tt = tid; tt < 128 * 32; tt += 256) {
            int nl = tt >> 5, c4 = (tt & 31) * 4;
            float4 v = *(const float4*)&ts[nl * 132 + c4];
            *(float4*)&C[(size_t)(n0 + nl) * SEQ + m0 + c4] = v;
        }
    }
}

// ================= tgemm64: 128x64 tile, 3 CTAs/SM ==========================
// TWO=1: C = alpha*((Ah+Al)@B^T); TWO=0: C = alpha*(Ah@B^T) (Al unused).
// (+bias)(+relu)(+resid)(+split out)
#define SM_TOT64 (4 * STG_A + 2 * STG_B)    // 51200

template<int TWO>
__global__ void __launch_bounds__(256, 3)
tgemm64(const __half* __restrict__ Ah, const __half* __restrict__ Al,
        const __half* __restrict__ Bs,
        float* __restrict__ C, const float* __restrict__ bias,
        const float* __restrict__ resid,
        __half* __restrict__ spH, __half* __restrict__ spL,
        int K, int Nout, float alpha, int do_relu,
        size_t sA, size_t sB, size_t sC, size_t sSp)
{
    extern __shared__ __align__(16) char dsm[];
    const uint32_t base = smem_u32(dsm);
    const uint32_t uAh = base;
    const uint32_t uAl = base + 2 * STG_A;
    const uint32_t uBs = base + 4 * STG_A;

    const int tid = threadIdx.x, wid = tid >> 5, lane = tid & 31;
    const int m0 = blockIdx.y * 128, n0 = blockIdx.x * 64;
    const int bz = blockIdx.z;
    Ah += (size_t)bz * sA;  Al += (size_t)bz * sA;
    Bs += (size_t)bz * sB;
    if (C) C += (size_t)bz * sC;
    if (resid) resid += (size_t)bz * sC;

    const int wm = wid & 3, wn = wid >> 2;        // 4m x 2n warps
    const int mb = wm * 32, nb = wn * 32;

    const uint32_t aRow = (lane & 15);
    const uint32_t aCol = (lane >> 4) * 16;
    const uint32_t bRow = (lane & 7) + ((lane >> 4) << 3);
    const uint32_t bCol = ((lane >> 3) & 1) * 16;

    const int fr0 = tid >> 2, fc0 = (tid & 3);    // A rows 0-63 / B rows 0-63
    const int fr1 = fr0 + 64;                     // A rows 64-127
    const uint32_t so0 = fr0 * (RS * 2) + fc0 * 16;
    const uint32_t so1 = fr1 * (RS * 2) + fc0 * 16;

    float acc[2][4][4];
#pragma unroll
    for (int f = 0; f < 2; f++)
#pragma unroll
        for (int j = 0; j < 4; j++)
#pragma unroll
            for (int e = 0; e < 4; e++) acc[f][j][e] = 0.f;

#define ISSUE64(ck, st) do { \
    uint32_t oA = (uint32_t)(st) * STG_A; \
    uint32_t oB = (uint32_t)(st) * STG_B; \
    size_t kk = (size_t)(ck) * 32 + fc0 * 8; \
    size_t ga0 = (size_t)(m0 + fr0) * K + kk; \
    size_t ga1 = (size_t)(m0 + fr1) * K + kk; \
    size_t gb0 = (size_t)(n0 + fr0) * K + kk; \
    cp16(uAh + oA + so0, Ah + ga0); cp16(uAh + oA + so1, Ah + ga1); \
    if (TWO) { cp16(uAl + oA + so0, Al + ga0); cp16(uAl + oA + so1, Al + ga1); } \
    cp16(uBs + oB + so0, Bs + gb0); \
    CP_COMMIT(); \
} while (0)

    const int nck = K >> 5;
    ISSUE64(0, 0);
    for (int ck = 0; ck < nck; ck++) {
        const int st = ck & 1;
        if (ck + 1 < nck) {
            ISSUE64(ck + 1, (ck + 1) & 1);
            asm volatile("cp.async.wait_group 1;" ::: "memory");
        } else {
            asm volatile("cp.async.wait_group 0;" ::: "memory");
        }
        __syncthreads();

        const uint32_t oAh = uAh + st * STG_A;
        const uint32_t oAl = uAl + st * STG_A;
        const uint32_t oBs = uBs + st * STG_B;
#pragma unroll
        for (int kh = 0; kh < 2; kh++) {
            const uint32_t kb = kh * 32;
            uint32_t ah[2][4], al[2][4];
            ldsm_x4(ah[0], oAh + (mb + aRow)      * (RS * 2) + kb + aCol);
            ldsm_x4(ah[1], oAh + (mb + 16 + aRow) * (RS * 2) + kb + aCol);
            if (TWO) {
                ldsm_x4(al[0], oAl + (mb + aRow)      * (RS * 2) + kb + aCol);
                ldsm_x4(al[1], oAl + (mb + 16 + aRow) * (RS * 2) + kb + aCol);
            }
#pragma unroll
            for (int g = 0; g < 2; g++) {
                uint32_t bh[4];
                ldsm_x4(bh, oBs + (nb + g * 16 + bRow) * (RS * 2) + kb + bCol);
#pragma unroll
                for (int f = 0; f < 2; f++) {
#pragma unroll
                    for (int nn = 0; nn < 2; nn++) {
                        float* cc = acc[f][g * 2 + nn];
                        mma16816(cc, ah[f], bh[2 * nn], bh[2 * nn + 1]);
                        if (TWO) mma16816(cc, al[f], bh[2 * nn], bh[2 * nn + 1]);
                    }
                }
            }
        }
        __syncthreads();
    }

    const int tg = lane >> 2, tig = lane & 3;
#pragma unroll
    for (int f = 0; f < 2; f++) {
        int r0 = m0 + mb + f * 16 + tg;
        float* c0 = C ? C + (size_t)r0 * Nout : nullptr;
        float* c1 = C ? C + (size_t)(r0 + 8) * Nout : nullptr;
        const float* rr0 = resid ? resid + (size_t)r0 * Nout : nullptr;
        const float* rr1 = resid ? resid + (size_t)(r0 + 8) * Nout : nullptr;
        __half* sh0 = spH ? spH + (size_t)bz * sSp + (size_t)r0 * KP : nullptr;
        __half* sh1 = spH ? spH + (size_t)bz * sSp + (size_t)(r0 + 8) * KP : nullptr;
        __half* sl0 = spL ? spL + (size_t)bz * sSp + (size_t)r0 * KP : nullptr;
        __half* sl1 = spL ? spL + (size_t)bz * sSp + (size_t)(r0 + 8) * KP : nullptr;
#pragma unroll
        for (int j = 0; j < 4; j++) {
            int cb = n0 + nb + j * 8 + tig * 2;
            float* a = acc[f][j];
#pragma unroll
            for (int e = 0; e < 2; e++) {
                int col = cb + e;
                if (col < Nout) {
                    float v0 = a[e] * alpha, v1 = a[e + 2] * alpha;
                    if (bias) { v0 += bias[col]; v1 += bias[col]; }
                    if (do_relu) { v0 = fmaxf(v0, 0.f); v1 = fmaxf(v1, 0.f); }
                    if (rr0) { v0 += rr0[col]; v1 += rr1[col]; }
                    if (c0) { c0[col] = v0; c1[col] = v1; }
                    if (sh0) {
                        split_store(v0, sh0, sl0, (size_t)col);
                        split_store(v1, sh1, sl1, (size_t)col);
                    }
                }
            }
        }
    }
}

// ================= softmax: fp32 scores -> single-fp16 probabilities ========
__global__ void __launch_bounds__(256) softmax_rows_k(const float* __restrict__ S,
                                                      __half* __restrict__ Ph) {
    size_t row = blockIdx.x;
    const float* rp = S + row * SEQ;
    int t = threadIdx.x;
    float4 v = ((const float4*)rp)[t];
    float m = fmaxf(fmaxf(v.x, v.y), fmaxf(v.z, v.w));
#pragma unroll
    for (int o = 16; o; o >>= 1) m = fmaxf(m, __shfl_xor_sync(0xffffffffu, m, o));
    __shared__ float red[8], red2[8];
    if ((t & 31) == 0) red[t >> 5] = m;
    __syncthreads();
    m = red[0];
#pragma unroll
    for (int i = 1; i < 8; i++) m = fmaxf(m, red[i]);
    v.x = __expf(v.x - m); v.y = __expf(v.y - m);
    v.z = __expf(v.z - m); v.w = __expf(v.w - m);
    float s = v.x + v.y + v.z + v.w;
#pragma unroll
    for (int o = 16; o; o >>= 1) s += __shfl_xor_sync(0xffffffffu, s, o);
    if ((t & 31) == 0) red2[t >> 5] = s;
    __syncthreads();
    s = 0.f;
#pragma unroll
    for (int i = 0; i < 8; i++) s += red2[i];
    float inv = 1.0f / s;
    size_t o2 = (row * SEQ) / 2 + 2 * t;
    ((__half2*)Ph)[o2]     = __halves2half2(__float2half(v.x * inv), __float2half(v.y * inv));
    ((__half2*)Ph)[o2 + 1] = __halves2half2(__float2half(v.z * inv), __float2half(v.w * inv));
}

// ================= layernorm (two-pass over [SEQ,EMB] per batch) ============
__global__ void __launch_bounds__(256) ln2_pass1(const float* __restrict__ y) {
    int b = blockIdx.x, ch = blockIdx.y;
    const float* p = y + (size_t)b * NE + (size_t)ch * CHUNK;
    int t = threadIdx.x;
    double s = 0.0, s2 = 0.0;
    for (int i = t; i < CHUNK; i += 256) {
        float v = p[i];
        s += (double)v; s2 += (double)v * (double)v;
    }
#pragma unroll
    for (int o = 16; o; o >>= 1) {
        s  += __shfl_xor_sync(0xffffffffu, s,  o);
        s2 += __shfl_xor_sync(0xffffffffu, s2, o);
    }
    __shared__ double rs[8], rs2[8];
    if ((t & 31) == 0) { rs[t >> 5] = s; rs2[t >> 5] = s2; }
    __syncthreads();
    if (t == 0) {
        double S = 0.0, S2 = 0.0;
        for (int i = 0; i < 8; i++) { S += rs[i]; S2 += rs2[i]; }
        g_ps [b * LNCH + ch] = S;
        g_ps2[b * LNCH + ch] = S2;
    }
}

__global__ void __launch_bounds__(256) ln2_pass2(const float* __restrict__ y,
                                                 float* __restrict__ out,
                                                 __half* __restrict__ oh,
                                                 __half* __restrict__ ol) {
    int b = blockIdx.x, ch = blockIdx.y;
    double S = 0.0, S2 = 0.0;
    for (int i = 0; i < LNCH; i++) { S += g_ps[b * LNCH + i]; S2 += g_ps2[b * LNCH + i]; }
    const double n = (double)NE;
    double mu = S / n, var = S2 / n - mu * mu;
    float muf = (float)mu;
    float inv = (float)(1.0 / sqrt(var + 1e-5));
    size_t base = (size_t)b * NE + (size_t)ch * CHUNK;
    for (int i = threadIdx.x; i < CHUNK; i += 256) {
        size_t e = base + i;
        float v = (y[e] - muf) * inv;
        out[e] = v;
        if (oh) {
            size_t r = e / EMB;
            int    k = (int)(e - r * EMB);
            split_store(v, oh, ol, r * KP + k);
        }
    }
}

// ================= host orchestration =======================================
extern "C" void kernel_launch(void* const* d_in, const int* in_sizes, int n_in,
                              void* d_out, int out_size)
{
    const int*   x      = (const int*)  d_in[0];
    const float* embed  = (const float*)d_in[1];
    const float* w_qkv  = (const float*)d_in[2];
    const float* b_qkv  = (const float*)d_in[3];
    const float* w_fuse = (const float*)d_in[4];
    const float* b_fuse = (const float*)d_in[5];
    const float* w1     = (const float*)d_in[6];
    const float* b1     = (const float*)d_in[7];
    const float* w2     = (const float*)d_in[8];
    const float* b2     = (const float*)d_in[9];
    float*       out    = (float*)d_out;
    (void)in_sizes; (void)n_in; (void)out_size;

    cudaFuncSetAttribute(tgemm128_score, cudaFuncAttributeMaxDynamicSharedMemorySize, SM_TOT128);
    cudaFuncSetAttribute(tgemm64<1>, cudaFuncAttributeMaxDynamicSharedMemorySize, SM_TOT64);
    cudaFuncSetAttribute(tgemm64<0>, cudaFuncAttributeMaxDynamicSharedMemorySize, SM_TOT64);

    float *h, *q, *y, *S, *wfe;
    cudaGetSymbolAddress((void**)&h,   g_h);
    cudaGetSymbolAddress((void**)&q,   g_q);
    cudaGetSymbolAddress((void**)&y,   g_y);
    cudaGetSymbolAddress((void**)&S,   g_S);
    cudaGetSymbolAddress((void**)&wfe, g_wfe);
    __half *Ahp,*Alp,*Chp,*Clp,*Qhp,*Qlp,*QTp,*Php,*Wq,*Wf,*W1,*W2;
    cudaGetSymbolAddress((void**)&Ahp, g_Ah);  cudaGetSymbolAddress((void**)&Alp, g_Al);
    cudaGetSymbolAddress((void**)&Chp, g_Ch);  cudaGetSymbolAddress((void**)&Clp, g_Cl);
    cudaGetSymbolAddress((void**)&Qhp, g_Qh);  cudaGetSymbolAddress((void**)&Qlp, g_Ql);
    cudaGetSymbolAddress((void**)&QTp, g_QT);
    cudaGetSymbolAddress((void**)&Php, g_Ph);
    cudaGetSymbolAddress((void**)&Wq,  g_Wq);  cudaGetSymbolAddress((void**)&Wf,  g_Wf);
    cudaGetSymbolAddress((void**)&W1,  g_W1);  cudaGetSymbolAddress((void**)&W2,  g_W2);

    const float inv_scale = 1.0f / sqrtf(200.0f);

    dim3 gFull(4, MROWS / 128, 1);
    dim3 gScoreSym(36, 1, BATCH);
    dim3 gCtx(4, SEQ / 128, BATCH);
    dim3 gTq(SEQ / 32, NP / 32, BATCH);
    dim3 bTq(32, 8);
    dim3 gLN(BATCH, LNCH);
    const size_t sQK = (size_t)SEQ * KP;
    const size_t sSS = (size_t)SEQ * SEQ;
    const size_t sQT = (size_t)NP * SEQ;

    // launch order keeps capture slot (4th launch) = tgemm64<1> (q-projection)
    count_zeros_k<<<BATCH, 256>>>(x);                                   // 1
    embed_pos_k  <<<MROWS, 256>>>(x, embed);                            // 2
    wtsplit_k<<<(NP * KP) / 256, 256>>>(w_qkv, Wq);                     // 3

    for (int s = 0; s < NSTACK; s++) {
        // q = h @ w_qkv + b_qkv  (fp32 q + fp16 hi/lo split)
        tgemm64<1><<<gFull, 256, SM_TOT64>>>(Ahp, Alp, Wq, q, b_qkv, nullptr,
                                             Qhp, Qlp, KP, EMB, 1.f, 0, 0, 0, 0, 0);  // 4
        tqsplit_k<<<gTq, bTq>>>(q, QTp);
        // S = q q^T / sqrt(D): symmetric 36 upper tiles + mirror
        tgemm128_score<<<gScoreSym, 256, SM_TOT128>>>(Qhp, Qlp, Qhp, S,
                                                      KP, inv_scale, sQK, sSS);
        softmax_rows_k<<<MROWS, 256>>>(S, Php);
        if (s == 0) {
            build_wfe_k<<<(EMB * EMB + 255) / 256, 256>>>(w_fuse);
            wtsplit_k<<<(NP * KP) / 256, 256>>>(wfe, Wf);
            wtsplit_k<<<(NP * KP) / 256, 256>>>(w1,  W1);
            wtsplit_k<<<(NP * KP) / 256, 256>>>(w2,  W2);
        }
        // c = P @ q   (A = P single fp16, B = q^T single; split-only output)
        tgemm64<0><<<gCtx, 256, SM_TOT64>>>(Php, nullptr, QTp, nullptr, nullptr, nullptr,
                                            Chp, Clp, SEQ, EMB, 1.f, 0, sSS, sQT, 0, sQK);
        // y = c @ wfe + b_fuse + h
        tgemm64<1><<<gFull, 256, SM_TOT64>>>(Chp, Clp, Wf, y, b_fuse, h,
                                             nullptr, nullptr, KP, EMB, 1.f, 0, 0, 0, 0, 0);
        ln2_pass1<<<gLN, 256>>>(y);
        ln2_pass2<<<gLN, 256>>>(y, h, Ahp, Alp);
        // ffn: t = relu(h@w1+b1) (split-only) ; y = t@w2+b2+h
        tgemm64<1><<<gFull, 256, SM_TOT64>>>(Ahp, Alp, W1, nullptr, b1, nullptr,
                                             Chp, Clp, KP, EMB, 1.f, 1, 0, 0, 0, 0);
        tgemm64<1><<<gFull, 256, SM_TOT64>>>(Chp, Clp, W2, y, b2, h,
                                             nullptr, nullptr, KP, EMB, 1.f, 0, 0, 0, 0, 0);
        ln2_pass1<<<gLN, 256>>>(y);
        if (s == NSTACK - 1)
            ln2_pass2<<<gLN, 256>>>(y, out, nullptr, nullptr);
        else
            ln2_pass2<<<gLN, 256>>>(y, h, Ahp, Alp);
    }
}

// round 15
// speedup vs baseline: 1.1251x; 1.0591x over previous
#include <cuda_runtime.h>
#include <cuda_fp16.h>
#include <cstdint>
#include <math.h>

#define BATCH  32
#define SEQ    1024
#define EMB    200
#define NSTACK 6
#define NHEAD  8
#define MROWS  (BATCH * SEQ)          // 32768
#define KP     224                    // padded K (=7*32)
#define NP     256                    // padded B-operand row count
#define NE     (SEQ * EMB)
#define LNCH   16
#define CHUNK  (NE / LNCH)

// ================= scratch (device globals; zero-initialized) ===============
__device__ float  g_h [MROWS * EMB];
__device__ float  g_q [MROWS * EMB];
__device__ float  g_y [MROWS * EMB];
__device__ float  g_S [BATCH * SEQ * SEQ];
__device__ float  g_wfe[EMB * EMB];
__device__ int    g_off[BATCH];
__device__ double g_psum [BATCH];
__device__ double g_psum2[BATCH];
// fp16 operand buffers. Pad columns [EMB,KP) never written -> stay 0.
__device__ __half g_Ah [MROWS * KP],  g_Al [MROWS * KP];   // h split (A-side)
__device__ __half g_Ch [MROWS * KP],  g_Cl [MROWS * KP];   // c / relu split
__device__ __half g_Qh [MROWS * KP];                       // q single fp16 (score A+B)
__device__ __half g_QT [BATCH * NP * SEQ];                 // q^T single (B for ctx)
__device__ __half g_Ph [BATCH * SEQ * SEQ];                // softmax probs, single fp16
__device__ __half g_Wq [NP * KP], g_Wf [NP * KP];
__device__ __half g_W1 [NP * KP], g_W2 [NP * KP];

// ================= base-ISA asm helpers =====================================
__device__ __forceinline__ uint32_t smem_u32(const void* p) {
    uint32_t a;
    asm("{ .reg .u64 t; cvta.to.shared.u64 t, %1; cvt.u32.u64 %0, t; }" : "=r"(a) : "l"(p));
    return a;
}
__device__ __forceinline__ void ldsm_x4(uint32_t* r, uint32_t addr) {
    asm volatile("ldmatrix.sync.aligned.m8n8.x4.shared.b16 {%0,%1,%2,%3}, [%4];"
        : "=r"(r[0]), "=r"(r[1]), "=r"(r[2]), "=r"(r[3]) : "r"(addr));
}
__device__ __forceinline__ void mma16816(float* c, const uint32_t* a,
                                         uint32_t b0, uint32_t b1) {
    asm volatile("mma.sync.aligned.m16n8k16.row.col.f32.f16.f16.f32 "
        "{%0,%1,%2,%3}, {%4,%5,%6,%7}, {%8,%9}, {%0,%1,%2,%3};"
        : "+f"(c[0]), "+f"(c[1]), "+f"(c[2]), "+f"(c[3])
        : "r"(a[0]), "r"(a[1]), "r"(a[2]), "r"(a[3]), "r"(b0), "r"(b1));
}
__device__ __forceinline__ void cp16(uint32_t s, const void* g) {
    asm volatile("cp.async.cg.shared.global [%0], [%1], 16;" :: "r"(s), "l"(g));
}
#define CP_COMMIT() asm volatile("cp.async.commit_group;" ::: "memory")

__device__ __forceinline__ void split_store(float v, __half* oh, __half* ol, size_t i) {
    __half hh = __float2half(v);
    oh[i] = hh;
    ol[i] = __float2half(v - __half2float(hh));
}

// ================= prologue kernels =========================================
__global__ void count_zeros_k(const int* __restrict__ x) {
    int b = blockIdx.x;
    __shared__ int cnt;
    if (threadIdx.x == 0) cnt = 0;
    __syncthreads();
    int c = 0;
    for (int i = threadIdx.x; i < SEQ; i += blockDim.x) c += (x[b * SEQ + i] == 0);
    atomicAdd(&cnt, c);
    __syncthreads();
    if (threadIdx.x == 0) g_off[b] = cnt;
}

__global__ void embed_pos_k(const int* __restrict__ x, const float* __restrict__ embed) {
    int row = blockIdx.x;
    int b = row >> 10, l = row & 1023;
    int j = l - g_off[b];
    bool valid = (j >= 0);
    float sv = 0.f, cv = 0.f;
    if (valid) {
        double jf  = (double)j;
        double ang = jf / pow(1000.0, jf / (double)EMB);
        sv = (float)sin(ang); cv = (float)cos(ang);
    }
    int tok = x[row];
    const float* er = embed + (size_t)tok * EMB;
    float*       hr = g_h   + (size_t)row * EMB;
    for (int k = threadIdx.x; k < EMB; k += blockDim.x) {
        float p = valid ? ((k & 1) ? sv : cv) : 0.f;
        float v = er[k] + p;
        hr[k] = v;
        split_store(v, g_Ah, g_Al, (size_t)row * KP + k);
    }
}

__global__ void build_wfe_k(const float* __restrict__ w_fuse) {
    int i = blockIdx.x * blockDim.x + threadIdx.x;
    if (i >= EMB * EMB) return;
    int d = i / EMB, n = i % EMB;
    float s = 0.f;
    for (int h = 0; h < NHEAD; h++) s += w_fuse[(size_t)(h * EMB + d) * EMB + n];
    g_wfe[i] = s;
}

__global__ void zero_ps_k() {
    int t = threadIdx.x;
    if (t < BATCH) { g_psum[t] = 0.0; g_psum2[t] = 0.0; }
}

// weight [EMB,EMB] -> transposed single fp16 [NP,KP]: out[n][k] = w[k][n]
__global__ void __launch_bounds__(256) wtsplit_k(const float* __restrict__ w,
                                                 __half* __restrict__ o) {
    int i = blockIdx.x * 256 + threadIdx.x;
    int n = i / KP, k = i % KP;
    float v = (n < EMB && k < EMB) ? w[k * EMB + n] : 0.f;
    o[i] = __float2half(v);
}

// q [B*SEQ, EMB] -> per-batch transposed single fp16 [B][NP][SEQ]
__global__ void tqsplit_k(const float* __restrict__ q, __half* __restrict__ o) {
    __shared__ float t[32][33];
    int b = blockIdx.z;
    int k0 = blockIdx.x * 32, n0 = blockIdx.y * 32;
    int tx = threadIdx.x, ty = threadIdx.y;   // (32, 8)
#pragma unroll
    for (int j = 0; j < 4; j++) {
        int k = k0 + ty + j * 8, n = n0 + tx;
        t[ty + j * 8][tx] = (n < EMB) ? q[((size_t)b * SEQ + k) * EMB + n] : 0.f;
    }
    __syncthreads();
#pragma unroll
    for (int j = 0; j < 4; j++) {
        int n = n0 + ty + j * 8, k = k0 + tx;
        o[(size_t)b * NP * SEQ + (size_t)n * SEQ + k] = __float2half(t[tx][ty + j * 8]);
    }
}

// ================= shared tiling constants ==================================
#define RS 40                          // smem row stride in halfs (80B)
#define STG_A (128 * RS * 2)           // 10240 B per 128-row array per stage
#define STG_B (64 * RS * 2)            // 5120 B per 64-row array per stage

// ================= tgemm128: 128x128 symmetric score GEMM (1-term fp16) =====
// S = alpha * A @ A^T (single fp16 both sides), upper-tri tile map + mirror.
#define SM_TOT128 69632                // transpose buffer 128*132*4 dominates

__global__ void __launch_bounds__(256, 2)
tgemm128_score(const __half* __restrict__ Ah, float* __restrict__ C,
               int K, float alpha, size_t sA, size_t sC)
{
    extern __shared__ __align__(16) char dsm[];
    const uint32_t base = smem_u32(dsm);
    const uint32_t uAh = base;
    const uint32_t uBs = base + 2 * STG_A;

    const int tid = threadIdx.x, wid = tid >> 5, lane = tid & 31;
    int t = blockIdx.x, ti = 0;
    while (t >= 8 - ti) { t -= 8 - ti; ti++; }
    const int tj = ti + t;
    const int m0 = ti * 128, n0 = tj * 128;
    const int bz = blockIdx.z;
    Ah += (size_t)bz * sA;
    C  += (size_t)bz * sC;

    const int wm = wid & 3, wn = wid >> 2;
    const int mb = wm * 32, nb = wn * 64;

    const uint32_t aRow = (lane & 15);
    const uint32_t aCol = (lane >> 4) * 16;
    const uint32_t bRow = (lane & 7) + ((lane >> 4) << 3);
    const uint32_t bCol = ((lane >> 3) & 1) * 16;

    const int fr0 = tid >> 2, fc0 = (tid & 3);
    const int fr1 = fr0 + 64;
    const uint32_t so0 = fr0 * (RS * 2) + fc0 * 16;
    const uint32_t so1 = fr1 * (RS * 2) + fc0 * 16;

    float acc[2][8][4];
#pragma unroll
    for (int f = 0; f < 2; f++)
#pragma unroll
        for (int j = 0; j < 8; j++)
#pragma unroll
            for (int e = 0; e < 4; e++) acc[f][j][e] = 0.f;

#define ISSUE128(ck, st) do { \
    uint32_t o = (uint32_t)(st) * STG_A; \
    size_t kk = (size_t)(ck) * 32 + fc0 * 8; \
    size_t ga0 = (size_t)(m0 + fr0) * K + kk; \
    size_t ga1 = (size_t)(m0 + fr1) * K + kk; \
    size_t gb0 = (size_t)(n0 + fr0) * K + kk; \
    size_t gb1 = (size_t)(n0 + fr1) * K + kk; \
    cp16(uAh + o + so0, Ah + ga0); cp16(uAh + o + so1, Ah + ga1); \
    cp16(uBs + o + so0, Ah + gb0); cp16(uBs + o + so1, Ah + gb1); \
    CP_COMMIT(); \
} while (0)

    const int nck = K >> 5;
    ISSUE128(0, 0);
    for (int ck = 0; ck < nck; ck++) {
        const int st = ck & 1;
        if (ck + 1 < nck) {
            ISSUE128(ck + 1, (ck + 1) & 1);
            asm volatile("cp.async.wait_group 1;" ::: "memory");
        } else {
            asm volatile("cp.async.wait_group 0;" ::: "memory");
        }
        __syncthreads();

        const uint32_t oAh = uAh + st * STG_A;
        const uint32_t oBs = uBs + st * STG_A;
#pragma unroll
        for (int kh = 0; kh < 2; kh++) {
            const uint32_t kb = kh * 32;
            uint32_t ah[2][4];
            ldsm_x4(ah[0], oAh + (mb + aRow)      * (RS * 2) + kb + aCol);
            ldsm_x4(ah[1], oAh + (mb + 16 + aRow) * (RS * 2) + kb + aCol);
#pragma unroll
            for (int g = 0; g < 4; g++) {
                uint32_t bh[4];
                ldsm_x4(bh, oBs + (nb + g * 16 + bRow) * (RS * 2) + kb + bCol);
#pragma unroll
                for (int f = 0; f < 2; f++) {
#pragma unroll
                    for (int nn = 0; nn < 2; nn++) {
                        float* cc = acc[f][g * 2 + nn];
                        mma16816(cc, ah[f], bh[2 * nn], bh[2 * nn + 1]);
                    }
                }
            }
        }
        __syncthreads();
    }

    const int tg = lane >> 2, tig = lane & 3;
    float* ts = (float*)dsm;               // 128x132 transpose buffer
#pragma unroll
    for (int f = 0; f < 2; f++) {
        int rl0 = mb + f * 16 + tg;
        float* c0 = C + (size_t)(m0 + rl0) * SEQ;
        float* c1 = C + (size_t)(m0 + rl0 + 8) * SEQ;
#pragma unroll
        for (int j = 0; j < 8; j++) {
            float* a = acc[f][j];
#pragma unroll
            for (int e = 0; e < 2; e++) {
                int cl = nb + j * 8 + tig * 2 + e;
                float v0 = a[e] * alpha, v1 = a[e + 2] * alpha;
                c0[n0 + cl] = v0;
                c1[n0 + cl] = v1;
                ts[cl * 132 + rl0]     = v0;
                ts[cl * 132 + rl0 + 8] = v1;
            }
        }
    }
    __syncthreads();
    if (ti != tj) {
        for (int tt = tid; tt < 128 * 32; tt += 256) {
            int nl = tt >> 5, c4 = (tt & 31) * 4;
            float4 v = *(const float4*)&ts[nl * 132 + c4];
            *(float4*)&C[(size_t)(n0 + nl) * SEQ + m0 + c4] = v;
        }
    }
}

// ================= tgemm64: 128x64 tile, 3 CTAs/SM ==========================
// TWO: 2-term A (hi+lo) vs 1-term. LNACC: accumulate per-batch sum/sumsq of
// written outputs into g_psum/g_psum2 (rows of one tile are within one batch).
// spL may be nullptr: hi-only fp16 output.
#define SM_TOT64 (4 * STG_A + 2 * STG_B)    // 51200

template<int TWO, int LNACC>
__global__ void __launch_bounds__(256, 3)
tgemm64(const __half* __restrict__ Ah, const __half* __restrict__ Al,
        const __half* __restrict__ Bs,
        float* __restrict__ C, const float* __restrict__ bias,
        const float* __restrict__ resid,
        __half* __restrict__ spH, __half* __restrict__ spL,
        int K, int Nout, float alpha, int do_relu,
        size_t sA, size_t sB, size_t sC, size_t sSp)
{
    extern __shared__ __align__(16) char dsm[];
    const uint32_t base = smem_u32(dsm);
    const uint32_t uAh = base;
    const uint32_t uAl = base + 2 * STG_A;
    const uint32_t uBs = base + 4 * STG_A;

    const int tid = threadIdx.x, wid = tid >> 5, lane = tid & 31;
    const int m0 = blockIdx.y * 128, n0 = blockIdx.x * 64;
    const int bz = blockIdx.z;
    Ah += (size_t)bz * sA;  Al += (size_t)bz * sA;
    Bs += (size_t)bz * sB;
    if (C) C += (size_t)bz * sC;
    if (resid) resid += (size_t)bz * sC;

    const int wm = wid & 3, wn = wid >> 2;        // 4m x 2n warps
    const int mb = wm * 32, nb = wn * 32;

    const uint32_t aRow = (lane & 15);
    const uint32_t aCol = (lane >> 4) * 16;
    const uint32_t bRow = (lane & 7) + ((lane >> 4) << 3);
    const uint32_t bCol = ((lane >> 3) & 1) * 16;

    const int fr0 = tid >> 2, fc0 = (tid & 3);
    const int fr1 = fr0 + 64;
    const uint32_t so0 = fr0 * (RS * 2) + fc0 * 16;
    const uint32_t so1 = fr1 * (RS * 2) + fc0 * 16;

    float acc[2][4][4];
#pragma unroll
    for (int f = 0; f < 2; f++)
#pragma unroll
        for (int j = 0; j < 4; j++)
#pragma unroll
            for (int e = 0; e < 4; e++) acc[f][j][e] = 0.f;

#define ISSUE64(ck, st) do { \
    uint32_t oA = (uint32_t)(st) * STG_A; \
    uint32_t oB = (uint32_t)(st) * STG_B; \
    size_t kk = (size_t)(ck) * 32 + fc0 * 8; \
    size_t ga0 = (size_t)(m0 + fr0) * K + kk; \
    size_t ga1 = (size_t)(m0 + fr1) * K + kk; \
    size_t gb0 = (size_t)(n0 + fr0) * K + kk; \
    cp16(uAh + oA + so0, Ah + ga0); cp16(uAh + oA + so1, Ah + ga1); \
    if (TWO) { cp16(uAl + oA + so0, Al + ga0); cp16(uAl + oA + so1, Al + ga1); } \
    cp16(uBs + oB + so0, Bs + gb0); \
    CP_COMMIT(); \
} while (0)

    const int nck = K >> 5;
    ISSUE64(0, 0);
    for (int ck = 0; ck < nck; ck++) {
        const int st = ck & 1;
        if (ck + 1 < nck) {
            ISSUE64(ck + 1, (ck + 1) & 1);
            asm volatile("cp.async.wait_group 1;" ::: "memory");
        } else {
            asm volatile("cp.async.wait_group 0;" ::: "memory");
        }
        __syncthreads();

        const uint32_t oAh = uAh + st * STG_A;
        const uint32_t oAl = uAl + st * STG_A;
        const uint32_t oBs = uBs + st * STG_B;
#pragma unroll
        for (int kh = 0; kh < 2; kh++) {
            const uint32_t kb = kh * 32;
            uint32_t ah[2][4], al[2][4];
            ldsm_x4(ah[0], oAh + (mb + aRow)      * (RS * 2) + kb + aCol);
            ldsm_x4(ah[1], oAh + (mb + 16 + aRow) * (RS * 2) + kb + aCol);
            if (TWO) {
                ldsm_x4(al[0], oAl + (mb + aRow)      * (RS * 2) + kb + aCol);
                ldsm_x4(al[1], oAl + (mb + 16 + aRow) * (RS * 2) + kb + aCol);
            }
#pragma unroll
            for (int g = 0; g < 2; g++) {
                uint32_t bh[4];
                ldsm_x4(bh, oBs + (nb + g * 16 + bRow) * (RS * 2) + kb + bCol);
#pragma unroll
                for (int f = 0; f < 2; f++) {
#pragma unroll
                    for (int nn = 0; nn < 2; nn++) {
                        float* cc = acc[f][g * 2 + nn];
                        mma16816(cc, ah[f], bh[2 * nn], bh[2 * nn + 1]);
                        if (TWO) mma16816(cc, al[f], bh[2 * nn], bh[2 * nn + 1]);
                    }
                }
            }
        }
        __syncthreads();
    }

    const int tg = lane >> 2, tig = lane & 3;
    double ls = 0.0, ls2 = 0.0;
#pragma unroll
    for (int f = 0; f < 2; f++) {
        int r0 = m0 + mb + f * 16 + tg;
        float* c0 = C ? C + (size_t)r0 * Nout : nullptr;
        float* c1 = C ? C + (size_t)(r0 + 8) * Nout : nullptr;
        const float* rr0 = resid ? resid + (size_t)r0 * Nout : nullptr;
        const float* rr1 = resid ? resid + (size_t)(r0 + 8) * Nout : nullptr;
        __half* sh0 = spH ? spH + (size_t)bz * sSp + (size_t)r0 * KP : nullptr;
        __half* sh1 = spH ? spH + (size_t)bz * sSp + (size_t)(r0 + 8) * KP : nullptr;
        __half* sl0 = spL ? spL + (size_t)bz * sSp + (size_t)r0 * KP : nullptr;
        __half* sl1 = spL ? spL + (size_t)bz * sSp + (size_t)(r0 + 8) * KP : nullptr;
#pragma unroll
        for (int j = 0; j < 4; j++) {
            int cb = n0 + nb + j * 8 + tig * 2;
            float* a = acc[f][j];
#pragma unroll
            for (int e = 0; e < 2; e++) {
                int col = cb + e;
                if (col < Nout) {
                    float v0 = a[e] * alpha, v1 = a[e + 2] * alpha;
                    if (bias) { v0 += bias[col]; v1 += bias[col]; }
                    if (do_relu) { v0 = fmaxf(v0, 0.f); v1 = fmaxf(v1, 0.f); }
                    if (rr0) { v0 += rr0[col]; v1 += rr1[col]; }
                    if (c0) { c0[col] = v0; c1[col] = v1; }
                    if (sh0) {
                        __half h0 = __float2half(v0), h1 = __float2half(v1);
                        sh0[col] = h0;
                        sh1[col] = h1;
                        if (sl0) {
                            sl0[col] = __float2half(v0 - __half2float(h0));
                            sl1[col] = __float2half(v1 - __half2float(h1));
                        }
                    }
                    if (LNACC) {
                        ls  += (double)v0 + (double)v1;
                        ls2 += (double)v0 * v0 + (double)v1 * v1;
                    }
                }
            }
        }
    }

    if (LNACC) {
#pragma unroll
        for (int o = 16; o; o >>= 1) {
            ls  += __shfl_xor_sync(0xffffffffu, ls,  o);
            ls2 += __shfl_xor_sync(0xffffffffu, ls2, o);
        }
        double* rp = (double*)dsm;     // stage buffers are dead now
        __syncthreads();
        if (lane == 0) { rp[wid] = ls; rp[8 + wid] = ls2; }
        __syncthreads();
        if (tid == 0) {
            double S = 0.0, S2 = 0.0;
#pragma unroll
            for (int i = 0; i < 8; i++) { S += rp[i]; S2 += rp[8 + i]; }
            int bb = m0 >> 10;         // tile rows lie within one batch
            atomicAdd(&g_psum[bb], S);
            atomicAdd(&g_psum2[bb], S2);
        }
    }
}

// ================= softmax: fp32 scores -> single-fp16 probabilities ========
__global__ void __launch_bounds__(256) softmax_rows_k(const float* __restrict__ S,
                                                      __half* __restrict__ Ph) {
    size_t row = blockIdx.x;
    const float* rp = S + row * SEQ;
    int t = threadIdx.x;
    float4 v = ((const float4*)rp)[t];
    float m = fmaxf(fmaxf(v.x, v.y), fmaxf(v.z, v.w));
#pragma unroll
    for (int o = 16; o; o >>= 1) m = fmaxf(m, __shfl_xor_sync(0xffffffffu, m, o));
    __shared__ float red[8], red2[8];
    if ((t & 31) == 0) red[t >> 5] = m;
    __syncthreads();
    m = red[0];
#pragma unroll
    for (int i = 1; i < 8; i++) m = fmaxf(m, red[i]);
    v.x = __expf(v.x - m); v.y = __expf(v.y - m);
    v.z = __expf(v.z - m); v.w = __expf(v.w - m);
    float s = v.x + v.y + v.z + v.w;
#pragma unroll
    for (int o = 16; o; o >>= 1) s += __shfl_xor_sync(0xffffffffu, s, o);
    if ((t & 31) == 0) red2[t >> 5] = s;
    __syncthreads();
    s = 0.f;
#pragma unroll
    for (int i = 0; i < 8; i++) s += red2[i];
    float inv = 1.0f / s;
    size_t o2 = (row * SEQ) / 2 + 2 * t;
    ((__half2*)Ph)[o2]     = __halves2half2(__float2half(v.x * inv), __float2half(v.y * inv));
    ((__half2*)Ph)[o2 + 1] = __halves2half2(__float2half(v.z * inv), __float2half(v.w * inv));
}

// ================= layernorm pass2 (stats precomputed by GEMM epilogue) =====
__global__ void __launch_bounds__(256) ln2_pass2(const float* __restrict__ y,
                                                 float* __restrict__ out,
                                                 __half* __restrict__ oh,
                                                 __half* __restrict__ ol) {
    int b = blockIdx.x, ch = blockIdx.y;
    const double n = (double)NE;
    double mu = g_psum[b] / n;
    double var = g_psum2[b] / n - mu * mu;
    float muf = (float)mu;
    float inv = (float)(1.0 / sqrt(var + 1e-5));
    size_t base = (size_t)b * NE + (size_t)ch * CHUNK;
    for (int i = threadIdx.x; i < CHUNK; i += 256) {
        size_t e = base + i;
        float v = (y[e] - muf) * inv;
        out[e] = v;
        if (oh) {
            size_t r = e / EMB;
            int    k = (int)(e - r * EMB);
            split_store(v, oh, ol, r * KP + k);
        }
    }
}

// ================= host orchestration =======================================
extern "C" void kernel_launch(void* const* d_in, const int* in_sizes, int n_in,
                              void* d_out, int out_size)
{
    const int*   x      = (const int*)  d_in[0];
    const float* embed  = (const float*)d_in[1];
    const float* w_qkv  = (const float*)d_in[2];
    const float* b_qkv  = (const float*)d_in[3];
    const float* w_fuse = (const float*)d_in[4];
    const float* b_fuse = (const float*)d_in[5];
    const float* w1     = (const float*)d_in[6];
    const float* b1     = (const float*)d_in[7];
    const float* w2     = (const float*)d_in[8];
    const float* b2     = (const float*)d_in[9];
    float*       out    = (float*)d_out;
    (void)in_sizes; (void)n_in; (void)out_size;

    cudaFuncSetAttribute(tgemm128_score, cudaFuncAttributeMaxDynamicSharedMemorySize, SM_TOT128);
    cudaFuncSetAttribute(tgemm64<1, 0>, cudaFuncAttributeMaxDynamicSharedMemorySize, SM_TOT64);
    cudaFuncSetAttribute(tgemm64<0, 0>, cudaFuncAttributeMaxDynamicSharedMemorySize, SM_TOT64);
    cudaFuncSetAttribute(tgemm64<1, 1>, cudaFuncAttributeMaxDynamicSharedMemorySize, SM_TOT64);

    float *h, *q, *y, *S, *wfe;
    cudaGetSymbolAddress((void**)&h,   g_h);
    cudaGetSymbolAddress((void**)&q,   g_q);
    cudaGetSymbolAddress((void**)&y,   g_y);
    cudaGetSymbolAddress((void**)&S,   g_S);
    cudaGetSymbolAddress((void**)&wfe, g_wfe);
    __half *Ahp,*Alp,*Chp,*Clp,*Qhp,*QTp,*Php,*Wq,*Wf,*W1,*W2;
    cudaGetSymbolAddress((void**)&Ahp, g_Ah);  cudaGetSymbolAddress((void**)&Alp, g_Al);
    cudaGetSymbolAddress((void**)&Chp, g_Ch);  cudaGetSymbolAddress((void**)&Clp, g_Cl);
    cudaGetSymbolAddress((void**)&Qhp, g_Qh);
    cudaGetSymbolAddress((void**)&QTp, g_QT);
    cudaGetSymbolAddress((void**)&Php, g_Ph);
    cudaGetSymbolAddress((void**)&Wq,  g_Wq);  cudaGetSymbolAddress((void**)&Wf,  g_Wf);
    cudaGetSymbolAddress((void**)&W1,  g_W1);  cudaGetSymbolAddress((void**)&W2,  g_W2);

    const float inv_scale = 1.0f / sqrtf(200.0f);

    dim3 gFull(4, MROWS / 128, 1);
    dim3 gScoreSym(36, 1, BATCH);
    dim3 gCtx(4, SEQ / 128, BATCH);
    dim3 gTq(SEQ / 32, NP / 32, BATCH);
    dim3 bTq(32, 8);
    dim3 gLN(BATCH, LNCH);
    const size_t sQK = (size_t)SEQ * KP;
    const size_t sSS = (size_t)SEQ * SEQ;
    const size_t sQT = (size_t)NP * SEQ;

    // launch order keeps capture slot (4th launch) = tgemm64<1,0> (q-proj)
    count_zeros_k<<<BATCH, 256>>>(x);                                   // 1
    embed_pos_k  <<<MROWS, 256>>>(x, embed);                            // 2
    wtsplit_k<<<(NP * KP) / 256, 256>>>(w_qkv, Wq);                     // 3

    for (int s = 0; s < NSTACK; s++) {
        // q = h @ w_qkv + b_qkv  (fp32 q + single-fp16 Qh; spL=null -> hi only)
        tgemm64<1, 0><<<gFull, 256, SM_TOT64>>>(Ahp, Alp, Wq, q, b_qkv, nullptr,
                                                Qhp, nullptr, KP, EMB, 1.f, 0,
                                                0, 0, 0, 0);            // 4
        tqsplit_k<<<gTq, bTq>>>(q, QTp);
        // S = fp16(q) fp16(q)^T / sqrt(D): symmetric 36 upper tiles + mirror
        tgemm128_score<<<gScoreSym, 256, SM_TOT128>>>(Qhp, S, KP, inv_scale, sQK, sSS);
        softmax_rows_k<<<MROWS, 256>>>(S, Php);
        if (s == 0) {
            build_wfe_k<<<(EMB * EMB + 255) / 256, 256>>>(w_fuse);
            wtsplit_k<<<(NP * KP) / 256, 256>>>(wfe, Wf);
            wtsplit_k<<<(NP * KP) / 256, 256>>>(w1,  W1);
            wtsplit_k<<<(NP * KP) / 256, 256>>>(w2,  W2);
        }
        // c = P @ q   (A = P single fp16, B = q^T single; split output)
        tgemm64<0, 0><<<gCtx, 256, SM_TOT64>>>(Php, nullptr, QTp, nullptr, nullptr,
                                               nullptr, Chp, Clp, SEQ, EMB, 1.f, 0,
                                               sSS, sQT, 0, sQK);
        // y = c @ wfe + b_fuse + h   (+ fused LN stats)
        zero_ps_k<<<1, 32>>>();
        tgemm64<1, 1><<<gFull, 256, SM_TOT64>>>(Chp, Clp, Wf, y, b_fuse, h,
                                                nullptr, nullptr, KP, EMB, 1.f, 0,
                                                0, 0, 0, 0);
        ln2_pass2<<<gLN, 256>>>(y, h, Ahp, Alp);
        // ffn: t = relu(h@w1+b1) (split-only) ; y = t@w2+b2+h (+ LN stats)
        tgemm64<1, 0><<<gFull, 256, SM_TOT64>>>(Ahp, Alp, W1, nullptr, b1, nullptr,
                                                Chp, Clp, KP, EMB, 1.f, 1,
                                                0, 0, 0, 0);
        zero_ps_k<<<1, 32>>>();
        tgemm64<1, 1><<<gFull, 256, SM_TOT64>>>(Chp, Clp, W2, y, b2, h,
                                                nullptr, nullptr, KP, EMB, 1.f, 0,
                                                0, 0, 0, 0);
        if (s == NSTACK - 1)
            ln2_pass2<<<gLN, 256>>>(y, out, nullptr, nullptr);
        else
            ln2_pass2<<<gLN, 256>>>(y, h, Ahp, Alp);
    }
}

// round 16
// speedup vs baseline: 1.2372x; 1.0996x over previous
#include <cuda_runtime.h>
#include <cuda_fp16.h>
#include <cstdint>
#include <math.h>

#define BATCH  32
#define SEQ    1024
#define EMB    200
#define NSTACK 6
#define NHEAD  8
#define MROWS  (BATCH * SEQ)          // 32768
#define KP     224                    // padded K (=7*32)
#define NP     256                    // padded B-operand row count
#define NE     (SEQ * EMB)
#define LNCH   16
#define CHUNK  (NE / LNCH)

// ================= scratch (device globals; zero-initialized) ===============
__device__ float  g_h [MROWS * EMB];
__device__ float  g_y [MROWS * EMB];
__device__ float  g_S [BATCH * SEQ * SEQ];
__device__ float  g_wfe[EMB * EMB];
__device__ int    g_off[BATCH];
__device__ double g_psum [BATCH];
__device__ double g_psum2[BATCH];
// fp16 operand buffers (all single precision fp16). Pad regions stay 0.
__device__ __half g_Ah [MROWS * KP];                       // h fp16 (A operand)
__device__ __half g_Ch [MROWS * KP];                       // c / relu-t fp16
__device__ __half g_Qh [MROWS * KP];                       // q fp16 (score A+B)
__device__ __half g_QT [BATCH * NP * SEQ];                 // q^T fp16 (B for ctx)
__device__ __half g_Ph [BATCH * SEQ * SEQ];                // softmax probs fp16
__device__ __half g_Wq [NP * KP], g_Wf [NP * KP];
__device__ __half g_W1 [NP * KP], g_W2 [NP * KP];

// ================= base-ISA asm helpers =====================================
__device__ __forceinline__ uint32_t smem_u32(const void* p) {
    uint32_t a;
    asm("{ .reg .u64 t; cvta.to.shared.u64 t, %1; cvt.u32.u64 %0, t; }" : "=r"(a) : "l"(p));
    return a;
}
__device__ __forceinline__ void ldsm_x4(uint32_t* r, uint32_t addr) {
    asm volatile("ldmatrix.sync.aligned.m8n8.x4.shared.b16 {%0,%1,%2,%3}, [%4];"
        : "=r"(r[0]), "=r"(r[1]), "=r"(r[2]), "=r"(r[3]) : "r"(addr));
}
__device__ __forceinline__ void mma16816(float* c, const uint32_t* a,
                                         uint32_t b0, uint32_t b1) {
    asm volatile("mma.sync.aligned.m16n8k16.row.col.f32.f16.f16.f32 "
        "{%0,%1,%2,%3}, {%4,%5,%6,%7}, {%8,%9}, {%0,%1,%2,%3};"
        : "+f"(c[0]), "+f"(c[1]), "+f"(c[2]), "+f"(c[3])
        : "r"(a[0]), "r"(a[1]), "r"(a[2]), "r"(a[3]), "r"(b0), "r"(b1));
}
__device__ __forceinline__ void cp16(uint32_t s, const void* g) {
    asm volatile("cp.async.cg.shared.global [%0], [%1], 16;" :: "r"(s), "l"(g));
}
#define CP_COMMIT() asm volatile("cp.async.commit_group;" ::: "memory")

// ================= prologue kernels =========================================
__global__ void count_zeros_k(const int* __restrict__ x) {
    int b = blockIdx.x;
    __shared__ int cnt;
    if (threadIdx.x == 0) cnt = 0;
    __syncthreads();
    int c = 0;
    for (int i = threadIdx.x; i < SEQ; i += blockDim.x) c += (x[b * SEQ + i] == 0);
    atomicAdd(&cnt, c);
    __syncthreads();
    if (threadIdx.x == 0) g_off[b] = cnt;
}

__global__ void embed_pos_k(const int* __restrict__ x, const float* __restrict__ embed) {
    int row = blockIdx.x;
    int b = row >> 10, l = row & 1023;
    int j = l - g_off[b];
    bool valid = (j >= 0);
    float sv = 0.f, cv = 0.f;
    if (valid) {
        double jf  = (double)j;
        double ang = jf / pow(1000.0, jf / (double)EMB);
        sv = (float)sin(ang); cv = (float)cos(ang);
    }
    int tok = x[row];
    const float* er = embed + (size_t)tok * EMB;
    float*       hr = g_h   + (size_t)row * EMB;
    for (int k = threadIdx.x; k < EMB; k += blockDim.x) {
        float p = valid ? ((k & 1) ? sv : cv) : 0.f;
        float v = er[k] + p;
        hr[k] = v;
        g_Ah[(size_t)row * KP + k] = __float2half(v);
    }
}

__global__ void build_wfe_k(const float* __restrict__ w_fuse) {
    int i = blockIdx.x * blockDim.x + threadIdx.x;
    if (i >= EMB * EMB) return;
    int d = i / EMB, n = i % EMB;
    float s = 0.f;
    for (int h = 0; h < NHEAD; h++) s += w_fuse[(size_t)(h * EMB + d) * EMB + n];
    g_wfe[i] = s;
}

__global__ void zero_ps_k() {
    int t = threadIdx.x;
    if (t < BATCH) { g_psum[t] = 0.0; g_psum2[t] = 0.0; }
}

// weight [EMB,EMB] -> transposed single fp16 [NP,KP]: out[n][k] = w[k][n]
__global__ void __launch_bounds__(256) wtsplit_k(const float* __restrict__ w,
                                                 __half* __restrict__ o) {
    int i = blockIdx.x * 256 + threadIdx.x;
    int n = i / KP, k = i % KP;
    float v = (n < EMB && k < EMB) ? w[k * EMB + n] : 0.f;
    o[i] = __float2half(v);
}

// ================= shared tiling constants ==================================
#define RS 40                          // smem row stride in halfs (80B)
#define STG_A (128 * RS * 2)           // 10240 B per 128-row array per stage
#define STG_B (64 * RS * 2)            // 5120 B per 64-row array per stage

// ================= tgemm128: 128x128 symmetric score GEMM (1-term fp16) =====
// S = alpha * A @ A^T (single fp16 both sides), upper-tri tile map + mirror.
#define SM_TOT128 69632                // transpose buffer 128*132*4 dominates

__global__ void __launch_bounds__(256, 2)
tgemm128_score(const __half* __restrict__ Ah, float* __restrict__ C,
               int K, float alpha, size_t sA, size_t sC)
{
    extern __shared__ __align__(16) char dsm[];
    const uint32_t base = smem_u32(dsm);
    const uint32_t uAh = base;
    const uint32_t uBs = base + 2 * STG_A;

    const int tid = threadIdx.x, wid = tid >> 5, lane = tid & 31;
    int t = blockIdx.x, ti = 0;
    while (t >= 8 - ti) { t -= 8 - ti; ti++; }
    const int tj = ti + t;
    const int m0 = ti * 128, n0 = tj * 128;
    const int bz = blockIdx.z;
    Ah += (size_t)bz * sA;
    C  += (size_t)bz * sC;

    const int wm = wid & 3, wn = wid >> 2;
    const int mb = wm * 32, nb = wn * 64;

    const uint32_t aRow = (lane & 15);
    const uint32_t aCol = (lane >> 4) * 16;
    const uint32_t bRow = (lane & 7) + ((lane >> 4) << 3);
    const uint32_t bCol = ((lane >> 3) & 1) * 16;

    const int fr0 = tid >> 2, fc0 = (tid & 3);
    const int fr1 = fr0 + 64;
    const uint32_t so0 = fr0 * (RS * 2) + fc0 * 16;
    const uint32_t so1 = fr1 * (RS * 2) + fc0 * 16;

    float acc[2][8][4];
#pragma unroll
    for (int f = 0; f < 2; f++)
#pragma unroll
        for (int j = 0; j < 8; j++)
#pragma unroll
            for (int e = 0; e < 4; e++) acc[f][j][e] = 0.f;

#define ISSUE128(ck, st) do { \
    uint32_t o = (uint32_t)(st) * STG_A; \
    size_t kk = (size_t)(ck) * 32 + fc0 * 8; \
    size_t ga0 = (size_t)(m0 + fr0) * K + kk; \
    size_t ga1 = (size_t)(m0 + fr1) * K + kk; \
    size_t gb0 = (size_t)(n0 + fr0) * K + kk; \
    size_t gb1 = (size_t)(n0 + fr1) * K + kk; \
    cp16(uAh + o + so0, Ah + ga0); cp16(uAh + o + so1, Ah + ga1); \
    cp16(uBs + o + so0, Ah + gb0); cp16(uBs + o + so1, Ah + gb1); \
    CP_COMMIT(); \
} while (0)

    const int nck = K >> 5;
    ISSUE128(0, 0);
    for (int ck = 0; ck < nck; ck++) {
        const int st = ck & 1;
        if (ck + 1 < nck) {
            ISSUE128(ck + 1, (ck + 1) & 1);
            asm volatile("cp.async.wait_group 1;" ::: "memory");
        } else {
            asm volatile("cp.async.wait_group 0;" ::: "memory");
        }
        __syncthreads();

        const uint32_t oAh = uAh + st * STG_A;
        const uint32_t oBs = uBs + st * STG_A;
#pragma unroll
        for (int kh = 0; kh < 2; kh++) {
            const uint32_t kb = kh * 32;
            uint32_t ah[2][4];
            ldsm_x4(ah[0], oAh + (mb + aRow)      * (RS * 2) + kb + aCol);
            ldsm_x4(ah[1], oAh + (mb + 16 + aRow) * (RS * 2) + kb + aCol);
#pragma unroll
            for (int g = 0; g < 4; g++) {
                uint32_t bh[4];
                ldsm_x4(bh, oBs + (nb + g * 16 + bRow) * (RS * 2) + kb + bCol);
#pragma unroll
                for (int f = 0; f < 2; f++) {
#pragma unroll
                    for (int nn = 0; nn < 2; nn++) {
                        float* cc = acc[f][g * 2 + nn];
                        mma16816(cc, ah[f], bh[2 * nn], bh[2 * nn + 1]);
                    }
                }
            }
        }
        __syncthreads();
    }

    const int tg = lane >> 2, tig = lane & 3;
    float* ts = (float*)dsm;               // 128x132 transpose buffer
#pragma unroll
    for (int f = 0; f < 2; f++) {
        int rl0 = mb + f * 16 + tg;
        float* c0 = C + (size_t)(m0 + rl0) * SEQ;
        float* c1 = C + (size_t)(m0 + rl0 + 8) * SEQ;
#pragma unroll
        for (int j = 0; j < 8; j++) {
            float* a = acc[f][j];
#pragma unroll
            for (int e = 0; e < 2; e++) {
                int cl = nb + j * 8 + tig * 2 + e;
                float v0 = a[e] * alpha, v1 = a[e + 2] * alpha;
                c0[n0 + cl] = v0;
                c1[n0 + cl] = v1;
                ts[cl * 132 + rl0]     = v0;
                ts[cl * 132 + rl0 + 8] = v1;
            }
        }
    }
    __syncthreads();
    if (ti != tj) {
        for (int tt = tid; tt < 128 * 32; tt += 256) {
            int nl = tt >> 5, c4 = (tt & 31) * 4;
            float4 v = *(const float4*)&ts[nl * 132 + c4];
            *(float4*)&C[(size_t)(n0 + nl) * SEQ + m0 + c4] = v;
        }
    }
}

// ================= tgemm64: 128x64 tile, single-fp16, 3 CTAs/SM =============
// C = alpha*(A @ B^T) (+bias)(+relu)(+resid); optional fp16 out (spH, KP
// stride) and transposed fp16 out (qtT: QT[b][col][row]). LNACC: per-batch
// sum/sumsq of outputs into g_psum/g_psum2.
#define SM_TOT64 (2 * STG_A + 2 * STG_B)    // 30720

template<int LNACC>
__global__ void __launch_bounds__(256, 3)
tgemm64(const __half* __restrict__ Ah, const __half* __restrict__ Bs,
        float* __restrict__ C, const float* __restrict__ bias,
        const float* __restrict__ resid,
        __half* __restrict__ spH, __half* __restrict__ qtT,
        int K, int Nout, float alpha, int do_relu,
        size_t sA, size_t sB, size_t sC, size_t sSp)
{
    extern __shared__ __align__(16) char dsm[];
    const uint32_t base = smem_u32(dsm);
    const uint32_t uAh = base;
    const uint32_t uBs = base + 2 * STG_A;

    const int tid = threadIdx.x, wid = tid >> 5, lane = tid & 31;
    const int m0 = blockIdx.y * 128, n0 = blockIdx.x * 64;
    const int bz = blockIdx.z;
    Ah += (size_t)bz * sA;
    Bs += (size_t)bz * sB;
    if (C) C += (size_t)bz * sC;
    if (resid) resid += (size_t)bz * sC;

    const int wm = wid & 3, wn = wid >> 2;        // 4m x 2n warps
    const int mb = wm * 32, nb = wn * 32;

    const uint32_t aRow = (lane & 15);
    const uint32_t aCol = (lane >> 4) * 16;
    const uint32_t bRow = (lane & 7) + ((lane >> 4) << 3);
    const uint32_t bCol = ((lane >> 3) & 1) * 16;

    const int fr0 = tid >> 2, fc0 = (tid & 3);
    const int fr1 = fr0 + 64;
    const uint32_t so0 = fr0 * (RS * 2) + fc0 * 16;
    const uint32_t so1 = fr1 * (RS * 2) + fc0 * 16;

    float acc[2][4][4];
#pragma unroll
    for (int f = 0; f < 2; f++)
#pragma unroll
        for (int j = 0; j < 4; j++)
#pragma unroll
            for (int e = 0; e < 4; e++) acc[f][j][e] = 0.f;

#define ISSUE64(ck, st) do { \
    uint32_t oA = (uint32_t)(st) * STG_A; \
    uint32_t oB = (uint32_t)(st) * STG_B; \
    size_t kk = (size_t)(ck) * 32 + fc0 * 8; \
    size_t ga0 = (size_t)(m0 + fr0) * K + kk; \
    size_t ga1 = (size_t)(m0 + fr1) * K + kk; \
    size_t gb0 = (size_t)(n0 + fr0) * K + kk; \
    cp16(uAh + oA + so0, Ah + ga0); cp16(uAh + oA + so1, Ah + ga1); \
    cp16(uBs + oB + so0, Bs + gb0); \
    CP_COMMIT(); \
} while (0)

    const int nck = K >> 5;
    ISSUE64(0, 0);
    for (int ck = 0; ck < nck; ck++) {
        const int st = ck & 1;
        if (ck + 1 < nck) {
            ISSUE64(ck + 1, (ck + 1) & 1);
            asm volatile("cp.async.wait_group 1;" ::: "memory");
        } else {
            asm volatile("cp.async.wait_group 0;" ::: "memory");
        }
        __syncthreads();

        const uint32_t oAh = uAh + st * STG_A;
        const uint32_t oBs = uBs + st * STG_B;
#pragma unroll
        for (int kh = 0; kh < 2; kh++) {
            const uint32_t kb = kh * 32;
            uint32_t ah[2][4];
            ldsm_x4(ah[0], oAh + (mb + aRow)      * (RS * 2) + kb + aCol);
            ldsm_x4(ah[1], oAh + (mb + 16 + aRow) * (RS * 2) + kb + aCol);
#pragma unroll
            for (int g = 0; g < 2; g++) {
                uint32_t bh[4];
                ldsm_x4(bh, oBs + (nb + g * 16 + bRow) * (RS * 2) + kb + bCol);
#pragma unroll
                for (int f = 0; f < 2; f++) {
#pragma unroll
                    for (int nn = 0; nn < 2; nn++) {
                        float* cc = acc[f][g * 2 + nn];
                        mma16816(cc, ah[f], bh[2 * nn], bh[2 * nn + 1]);
                    }
                }
            }
        }
        __syncthreads();
    }

    const int tg = lane >> 2, tig = lane & 3;
    __half* qtb = qtT ? qtT + (size_t)(m0 >> 10) * NP * SEQ : nullptr;
    double ls = 0.0, ls2 = 0.0;
#pragma unroll
    for (int f = 0; f < 2; f++) {
        int r0 = m0 + mb + f * 16 + tg;
        int rin = r0 & 1023;
        float* c0 = C ? C + (size_t)r0 * Nout : nullptr;
        float* c1 = C ? C + (size_t)(r0 + 8) * Nout : nullptr;
        const float* rr0 = resid ? resid + (size_t)r0 * Nout : nullptr;
        const float* rr1 = resid ? resid + (size_t)(r0 + 8) * Nout : nullptr;
        __half* sh0 = spH ? spH + (size_t)bz * sSp + (size_t)r0 * KP : nullptr;
        __half* sh1 = spH ? spH + (size_t)bz * sSp + (size_t)(r0 + 8) * KP : nullptr;
#pragma unroll
        for (int j = 0; j < 4; j++) {
            int cb = n0 + nb + j * 8 + tig * 2;
            float* a = acc[f][j];
#pragma unroll
            for (int e = 0; e < 2; e++) {
                int col = cb + e;
                if (col < Nout) {
                    float v0 = a[e] * alpha, v1 = a[e + 2] * alpha;
                    if (bias) { v0 += bias[col]; v1 += bias[col]; }
                    if (do_relu) { v0 = fmaxf(v0, 0.f); v1 = fmaxf(v1, 0.f); }
                    if (rr0) { v0 += rr0[col]; v1 += rr1[col]; }
                    if (c0) { c0[col] = v0; c1[col] = v1; }
                    __half h0 = __float2half(v0), h1 = __float2half(v1);
                    if (sh0) { sh0[col] = h0; sh1[col] = h1; }
                    if (qtb) {
                        qtb[(size_t)col * SEQ + rin]     = h0;
                        qtb[(size_t)col * SEQ + rin + 8] = h1;
                    }
                    if (LNACC) {
                        ls  += (double)v0 + (double)v1;
                        ls2 += (double)v0 * v0 + (double)v1 * v1;
                    }
                }
            }
        }
    }

    if (LNACC) {
#pragma unroll
        for (int o = 16; o; o >>= 1) {
            ls  += __shfl_xor_sync(0xffffffffu, ls,  o);
            ls2 += __shfl_xor_sync(0xffffffffu, ls2, o);
        }
        double* rp = (double*)dsm;     // stage buffers are dead now
        __syncthreads();
        if (lane == 0) { rp[wid] = ls; rp[8 + wid] = ls2; }
        __syncthreads();
        if (tid == 0) {
            double S = 0.0, S2 = 0.0;
#pragma unroll
            for (int i = 0; i < 8; i++) { S += rp[i]; S2 += rp[8 + i]; }
            int bb = m0 >> 10;         // tile rows lie within one batch
            atomicAdd(&g_psum[bb], S);
            atomicAdd(&g_psum2[bb], S2);
        }
    }
}

// ================= softmax: fp32 scores -> single-fp16 probabilities ========
__global__ void __launch_bounds__(256) softmax_rows_k(const float* __restrict__ S,
                                                      __half* __restrict__ Ph) {
    size_t row = blockIdx.x;
    const float* rp = S + row * SEQ;
    int t = threadIdx.x;
    float4 v = ((const float4*)rp)[t];
    float m = fmaxf(fmaxf(v.x, v.y), fmaxf(v.z, v.w));
#pragma unroll
    for (int o = 16; o; o >>= 1) m = fmaxf(m, __shfl_xor_sync(0xffffffffu, m, o));
    __shared__ float red[8], red2[8];
    if ((t & 31) == 0) red[t >> 5] = m;
    __syncthreads();
    m = red[0];
#pragma unroll
    for (int i = 1; i < 8; i++) m = fmaxf(m, red[i]);
    v.x = __expf(v.x - m); v.y = __expf(v.y - m);
    v.z = __expf(v.z - m); v.w = __expf(v.w - m);
    float s = v.x + v.y + v.z + v.w;
#pragma unroll
    for (int o = 16; o; o >>= 1) s += __shfl_xor_sync(0xffffffffu, s, o);
    if ((t & 31) == 0) red2[t >> 5] = s;
    __syncthreads();
    s = 0.f;
#pragma unroll
    for (int i = 0; i < 8; i++) s += red2[i];
    float inv = 1.0f / s;
    size_t o2 = (row * SEQ) / 2 + 2 * t;
    ((__half2*)Ph)[o2]     = __halves2half2(__float2half(v.x * inv), __float2half(v.y * inv));
    ((__half2*)Ph)[o2 + 1] = __halves2half2(__float2half(v.z * inv), __float2half(v.w * inv));
}

// ================= layernorm pass2 (stats precomputed by GEMM epilogue) =====
__global__ void __launch_bounds__(256) ln2_pass2(const float* __restrict__ y,
                                                 float* __restrict__ out,
                                                 __half* __restrict__ oh) {
    int b = blockIdx.x, ch = blockIdx.y;
    const double n = (double)NE;
    double mu = g_psum[b] / n;
    double var = g_psum2[b] / n - mu * mu;
    float muf = (float)mu;
    float inv = (float)(1.0 / sqrt(var + 1e-5));
    size_t base = (size_t)b * NE + (size_t)ch * CHUNK;
    for (int i = threadIdx.x; i < CHUNK; i += 256) {
        size_t e = base + i;
        float v = (y[e] - muf) * inv;
        out[e] = v;
        if (oh) {
            size_t r = e / EMB;
            int    k = (int)(e - r * EMB);
            oh[r * KP + k] = __float2half(v);
        }
    }
}

// ================= host orchestration =======================================
extern "C" void kernel_launch(void* const* d_in, const int* in_sizes, int n_in,
                              void* d_out, int out_size)
{
    const int*   x      = (const int*)  d_in[0];
    const float* embed  = (const float*)d_in[1];
    const float* w_qkv  = (const float*)d_in[2];
    const float* b_qkv  = (const float*)d_in[3];
    const float* w_fuse = (const float*)d_in[4];
    const float* b_fuse = (const float*)d_in[5];
    const float* w1     = (const float*)d_in[6];
    const float* b1     = (const float*)d_in[7];
    const float* w2     = (const float*)d_in[8];
    const float* b2     = (const float*)d_in[9];
    float*       out    = (float*)d_out;
    (void)in_sizes; (void)n_in; (void)out_size;

    cudaFuncSetAttribute(tgemm128_score, cudaFuncAttributeMaxDynamicSharedMemorySize, SM_TOT128);

    float *h, *y, *S, *wfe;
    cudaGetSymbolAddress((void**)&h,   g_h);
    cudaGetSymbolAddress((void**)&y,   g_y);
    cudaGetSymbolAddress((void**)&S,   g_S);
    cudaGetSymbolAddress((void**)&wfe, g_wfe);
    __half *Ahp,*Chp,*Qhp,*QTp,*Php,*Wq,*Wf,*W1,*W2;
    cudaGetSymbolAddress((void**)&Ahp, g_Ah);
    cudaGetSymbolAddress((void**)&Chp, g_Ch);
    cudaGetSymbolAddress((void**)&Qhp, g_Qh);
    cudaGetSymbolAddress((void**)&QTp, g_QT);
    cudaGetSymbolAddress((void**)&Php, g_Ph);
    cudaGetSymbolAddress((void**)&Wq,  g_Wq);  cudaGetSymbolAddress((void**)&Wf,  g_Wf);
    cudaGetSymbolAddress((void**)&W1,  g_W1);  cudaGetSymbolAddress((void**)&W2,  g_W2);

    const float inv_scale = 1.0f / sqrtf(200.0f);

    dim3 gFull(4, MROWS / 128, 1);
    dim3 gScoreSym(36, 1, BATCH);
    dim3 gCtx(4, SEQ / 128, BATCH);
    dim3 gLN(BATCH, LNCH);
    const size_t sQK = (size_t)SEQ * KP;
    const size_t sSS = (size_t)SEQ * SEQ;
    const size_t sQT = (size_t)NP * SEQ;

    // launch order keeps capture slot (4th launch) = tgemm64<0> (q-proj)
    count_zeros_k<<<BATCH, 256>>>(x);                                   // 1
    embed_pos_k  <<<MROWS, 256>>>(x, embed);                            // 2
    wtsplit_k<<<(NP * KP) / 256, 256>>>(w_qkv, Wq);                     // 3

    for (int s = 0; s < NSTACK; s++) {
        // q = h @ w_qkv + b_qkv  -> fp16 Qh (row-major) + QT (transposed)
        tgemm64<0><<<gFull, 256, SM_TOT64>>>(Ahp, Wq, nullptr, b_qkv, nullptr,
                                             Qhp, QTp, KP, EMB, 1.f, 0,
                                             0, 0, 0, 0);               // 4
        // S = fp16(q) fp16(q)^T / sqrt(D): symmetric 36 upper tiles + mirror
        tgemm128_score<<<gScoreSym, 256, SM_TOT128>>>(Qhp, S, KP, inv_scale, sQK, sSS);
        softmax_rows_k<<<MROWS, 256>>>(S, Php);
        if (s == 0) {
            build_wfe_k<<<(EMB * EMB + 255) / 256, 256>>>(w_fuse);
            wtsplit_k<<<(NP * KP) / 256, 256>>>(wfe, Wf);
            wtsplit_k<<<(NP * KP) / 256, 256>>>(w1,  W1);
            wtsplit_k<<<(NP * KP) / 256, 256>>>(w2,  W2);
        }
        // c = P @ q   (A = P fp16, B = q^T fp16; fp16 output only)
        tgemm64<0><<<gCtx, 256, SM_TOT64>>>(Php, QTp, nullptr, nullptr, nullptr,
                                            Chp, nullptr, SEQ, EMB, 1.f, 0,
                                            sSS, sQT, 0, sQK);
        // y = c @ wfe + b_fuse + h   (+ fused LN stats)
        zero_ps_k<<<1, 32>>>();
        tgemm64<1><<<gFull, 256, SM_TOT64>>>(Chp, Wf, y, b_fuse, h,
                                             nullptr, nullptr, KP, EMB, 1.f, 0,
                                             0, 0, 0, 0);
        ln2_pass2<<<gLN, 256>>>(y, h, Ahp);
        // ffn: t = relu(h@w1+b1) (fp16 out) ; y = t@w2+b2+h (+ LN stats)
        tgemm64<0><<<gFull, 256, SM_TOT64>>>(Ahp, W1, nullptr, b1, nullptr,
                                             Chp, nullptr, KP, EMB, 1.f, 1,
                                             0, 0, 0, 0);
        zero_ps_k<<<1, 32>>>();
        tgemm64<1><<<gFull, 256, SM_TOT64>>>(Chp, W2, y, b2, h,
                                             nullptr, nullptr, KP, EMB, 1.f, 0,
                                             0, 0, 0, 0);
        if (s == NSTACK - 1)
            ln2_pass2<<<gLN, 256>>>(y, out, nullptr);
        else
            ln2_pass2<<<gLN, 256>>>(y, h, Ahp);
    }
}

// round 17
// speedup vs baseline: 1.2462x; 1.0073x over previous
#include <cuda_runtime.h>
#include <cuda_fp16.h>
#include <cstdint>
#include <math.h>

#define BATCH  32
#define SEQ    1024
#define EMB    200
#define NSTACK 6
#define NHEAD  8
#define MROWS  (BATCH * SEQ)          // 32768
#define KP     224                    // padded K (=7*32)
#define NP     256                    // padded B-operand row count
#define NE     (SEQ * EMB)
#define LNCH   16
#define CHUNK  (NE / LNCH)

// ================= scratch (device globals; zero-initialized) ===============
__device__ float  g_h [MROWS * EMB];
__device__ float  g_y [MROWS * EMB];
__device__ __half g_S [BATCH * SEQ * SEQ];                 // fp16 scores
__device__ float  g_wfe[EMB * EMB];
__device__ int    g_off[BATCH];
__device__ double g_psum [BATCH];
__device__ double g_psum2[BATCH];
// fp16 operand buffers. Pad regions stay 0.
__device__ __half g_Ah [MROWS * KP];                       // h fp16 (A operand)
__device__ __half g_Ch [MROWS * KP];                       // c / relu-t fp16
__device__ __half g_Qh [MROWS * KP];                       // q fp16 (score A+B)
__device__ __half g_QT [BATCH * NP * SEQ];                 // q^T fp16 (B for ctx)
__device__ __half g_Ph [BATCH * SEQ * SEQ];                // softmax probs fp16
__device__ __half g_Wq [NP * KP], g_Wf [NP * KP];
__device__ __half g_W1 [NP * KP], g_W2 [NP * KP];

// ================= base-ISA asm helpers =====================================
__device__ __forceinline__ uint32_t smem_u32(const void* p) {
    uint32_t a;
    asm("{ .reg .u64 t; cvta.to.shared.u64 t, %1; cvt.u32.u64 %0, t; }" : "=r"(a) : "l"(p));
    return a;
}
__device__ __forceinline__ void ldsm_x4(uint32_t* r, uint32_t addr) {
    asm volatile("ldmatrix.sync.aligned.m8n8.x4.shared.b16 {%0,%1,%2,%3}, [%4];"
        : "=r"(r[0]), "=r"(r[1]), "=r"(r[2]), "=r"(r[3]) : "r"(addr));
}
__device__ __forceinline__ void mma16816(float* c, const uint32_t* a,
                                         uint32_t b0, uint32_t b1) {
    asm volatile("mma.sync.aligned.m16n8k16.row.col.f32.f16.f16.f32 "
        "{%0,%1,%2,%3}, {%4,%5,%6,%7}, {%8,%9}, {%0,%1,%2,%3};"
        : "+f"(c[0]), "+f"(c[1]), "+f"(c[2]), "+f"(c[3])
        : "r"(a[0]), "r"(a[1]), "r"(a[2]), "r"(a[3]), "r"(b0), "r"(b1));
}
__device__ __forceinline__ void cp16(uint32_t s, const void* g) {
    asm volatile("cp.async.cg.shared.global [%0], [%1], 16;" :: "r"(s), "l"(g));
}
#define CP_COMMIT() asm volatile("cp.async.commit_group;" ::: "memory")

// ================= prologue kernels =========================================
__global__ void count_zeros_k(const int* __restrict__ x) {
    int b = blockIdx.x;
    __shared__ int cnt;
    if (threadIdx.x == 0) cnt = 0;
    __syncthreads();
    int c = 0;
    for (int i = threadIdx.x; i < SEQ; i += blockDim.x) c += (x[b * SEQ + i] == 0);
    atomicAdd(&cnt, c);
    __syncthreads();
    if (threadIdx.x == 0) g_off[b] = cnt;
}

__global__ void embed_pos_k(const int* __restrict__ x, const float* __restrict__ embed) {
    int row = blockIdx.x;
    int b = row >> 10, l = row & 1023;
    int j = l - g_off[b];
    bool valid = (j >= 0);
    float sv = 0.f, cv = 0.f;
    if (valid) {
        double jf  = (double)j;
        double ang = jf / pow(1000.0, jf / (double)EMB);
        sv = (float)sin(ang); cv = (float)cos(ang);
    }
    int tok = x[row];
    const float* er = embed + (size_t)tok * EMB;
    float*       hr = g_h   + (size_t)row * EMB;
    for (int k = threadIdx.x; k < EMB; k += blockDim.x) {
        float p = valid ? ((k & 1) ? sv : cv) : 0.f;
        float v = er[k] + p;
        hr[k] = v;
        g_Ah[(size_t)row * KP + k] = __float2half(v);
    }
}

__global__ void build_wfe_k(const float* __restrict__ w_fuse) {
    int i = blockIdx.x * blockDim.x + threadIdx.x;
    if (i >= EMB * EMB) return;
    int d = i / EMB, n = i % EMB;
    float s = 0.f;
    for (int h = 0; h < NHEAD; h++) s += w_fuse[(size_t)(h * EMB + d) * EMB + n];
    g_wfe[i] = s;
}

__global__ void zero_ps_k() {
    int t = threadIdx.x;
    if (t < BATCH) { g_psum[t] = 0.0; g_psum2[t] = 0.0; }
}

// weight [EMB,EMB] -> transposed single fp16 [NP,KP]: out[n][k] = w[k][n]
__global__ void __launch_bounds__(256) wtsplit_k(const float* __restrict__ w,
                                                 __half* __restrict__ o) {
    int i = blockIdx.x * 256 + threadIdx.x;
    int n = i / KP, k = i % KP;
    float v = (n < EMB && k < EMB) ? w[k * EMB + n] : 0.f;
    o[i] = __float2half(v);
}

// ================= shared tiling constants ==================================
#define RS 40                          // smem row stride in halfs (80B)
#define STG_A (128 * RS * 2)           // 10240 B per 128-row array per stage
#define SM_TOT128 69632                // 4*STG_A stages; transpose buf 67584

// ================= tgemm128_score: symmetric S = a*A A^T, fp16 out ==========
__global__ void __launch_bounds__(256, 2)
tgemm128_score(const __half* __restrict__ Ah, __half* __restrict__ C,
               int K, float alpha, size_t sA, size_t sC)
{
    extern __shared__ __align__(16) char dsm[];
    const uint32_t base = smem_u32(dsm);
    const uint32_t uAh = base;
    const uint32_t uBs = base + 2 * STG_A;

    const int tid = threadIdx.x, wid = tid >> 5, lane = tid & 31;
    int t = blockIdx.x, ti = 0;
    while (t >= 8 - ti) { t -= 8 - ti; ti++; }
    const int tj = ti + t;
    const int m0 = ti * 128, n0 = tj * 128;
    const int bz = blockIdx.z;
    Ah += (size_t)bz * sA;
    C  += (size_t)bz * sC;

    const int wm = wid & 3, wn = wid >> 2;
    const int mb = wm * 32, nb = wn * 64;

    const uint32_t aRow = (lane & 15);
    const uint32_t aCol = (lane >> 4) * 16;
    const uint32_t bRow = (lane & 7) + ((lane >> 4) << 3);
    const uint32_t bCol = ((lane >> 3) & 1) * 16;

    const int fr0 = tid >> 2, fc0 = (tid & 3);
    const int fr1 = fr0 + 64;
    const uint32_t so0 = fr0 * (RS * 2) + fc0 * 16;
    const uint32_t so1 = fr1 * (RS * 2) + fc0 * 16;

    float acc[2][8][4];
#pragma unroll
    for (int f = 0; f < 2; f++)
#pragma unroll
        for (int j = 0; j < 8; j++)
#pragma unroll
            for (int e = 0; e < 4; e++) acc[f][j][e] = 0.f;

#define ISSUE_SC(ck, st) do { \
    uint32_t o = (uint32_t)(st) * STG_A; \
    size_t kk = (size_t)(ck) * 32 + fc0 * 8; \
    size_t ga0 = (size_t)(m0 + fr0) * K + kk; \
    size_t ga1 = (size_t)(m0 + fr1) * K + kk; \
    size_t gb0 = (size_t)(n0 + fr0) * K + kk; \
    size_t gb1 = (size_t)(n0 + fr1) * K + kk; \
    cp16(uAh + o + so0, Ah + ga0); cp16(uAh + o + so1, Ah + ga1); \
    cp16(uBs + o + so0, Ah + gb0); cp16(uBs + o + so1, Ah + gb1); \
    CP_COMMIT(); \
} while (0)

    const int nck = K >> 5;
    ISSUE_SC(0, 0);
    for (int ck = 0; ck < nck; ck++) {
        const int st = ck & 1;
        if (ck + 1 < nck) {
            ISSUE_SC(ck + 1, (ck + 1) & 1);
            asm volatile("cp.async.wait_group 1;" ::: "memory");
        } else {
            asm volatile("cp.async.wait_group 0;" ::: "memory");
        }
        __syncthreads();

        const uint32_t oAh = uAh + st * STG_A;
        const uint32_t oBs = uBs + st * STG_A;
#pragma unroll
        for (int kh = 0; kh < 2; kh++) {
            const uint32_t kb = kh * 32;
            uint32_t ah[2][4];
            ldsm_x4(ah[0], oAh + (mb + aRow)      * (RS * 2) + kb + aCol);
            ldsm_x4(ah[1], oAh + (mb + 16 + aRow) * (RS * 2) + kb + aCol);
#pragma unroll
            for (int g = 0; g < 4; g++) {
                uint32_t bh[4];
                ldsm_x4(bh, oBs + (nb + g * 16 + bRow) * (RS * 2) + kb + bCol);
#pragma unroll
                for (int f = 0; f < 2; f++) {
#pragma unroll
                    for (int nn = 0; nn < 2; nn++) {
                        float* cc = acc[f][g * 2 + nn];
                        mma16816(cc, ah[f], bh[2 * nn], bh[2 * nn + 1]);
                    }
                }
            }
        }
        __syncthreads();
    }

    const int tg = lane >> 2, tig = lane & 3;
    float* ts = (float*)dsm;               // 128x132 transpose buffer
#pragma unroll
    for (int f = 0; f < 2; f++) {
        int rl0 = mb + f * 16 + tg;
        __half* c0 = C + (size_t)(m0 + rl0) * SEQ;
        __half* c1 = C + (size_t)(m0 + rl0 + 8) * SEQ;
#pragma unroll
        for (int j = 0; j < 8; j++) {
            float* a = acc[f][j];
#pragma unroll
            for (int e = 0; e < 2; e++) {
                int cl = nb + j * 8 + tig * 2 + e;
                float v0 = a[e] * alpha, v1 = a[e + 2] * alpha;
                c0[n0 + cl] = __float2half(v0);
                c1[n0 + cl] = __float2half(v1);
                ts[cl * 132 + rl0]     = v0;
                ts[cl * 132 + rl0 + 8] = v1;
            }
        }
    }
    __syncthreads();
    if (ti != tj) {
        for (int tt = tid; tt < 128 * 32; tt += 256) {
            int nl = tt >> 5, c4 = (tt & 31) * 4;
            float4 v = *(const float4*)&ts[nl * 132 + c4];
            __half2 p0 = __halves2half2(__float2half(v.x), __float2half(v.y));
            __half2 p1 = __halves2half2(__float2half(v.z), __float2half(v.w));
            __half2* dst = (__half2*)&C[(size_t)(n0 + nl) * SEQ + m0 + c4];
            dst[0] = p0; dst[1] = p1;
        }
    }
}

// ================= tgemm128g: general 128x128 fp16 GEMM, 2 CTAs/SM ==========
// C = alpha*(A @ B^T) (+bias)(+relu)(+resid fp32); optional fp16 out (spH,
// KP stride), transposed fp16 out (qtT), per-batch LN stats (LNACC).
#define SM_TOTG (4 * STG_A)            // 40960

template<int LNACC>
__global__ void __launch_bounds__(256, 2)
tgemm128g(const __half* __restrict__ Ah, const __half* __restrict__ Bs,
          float* __restrict__ C, const float* __restrict__ bias,
          const float* __restrict__ resid,
          __half* __restrict__ spH, __half* __restrict__ qtT,
          int K, int Nout, float alpha, int do_relu,
          size_t sA, size_t sB, size_t sC, size_t sSp)
{
    extern __shared__ __align__(16) char dsm[];
    const uint32_t base = smem_u32(dsm);
    const uint32_t uAh = base;
    const uint32_t uBs = base + 2 * STG_A;

    const int tid = threadIdx.x, wid = tid >> 5, lane = tid & 31;
    const int m0 = blockIdx.y * 128, n0 = blockIdx.x * 128;
    const int bz = blockIdx.z;
    Ah += (size_t)bz * sA;
    Bs += (size_t)bz * sB;
    if (C) C += (size_t)bz * sC;
    if (resid) resid += (size_t)bz * sC;

    const int wm = wid & 3, wn = wid >> 2;        // 4m x 2n warps
    const int mb = wm * 32, nb = wn * 64;

    const uint32_t aRow = (lane & 15);
    const uint32_t aCol = (lane >> 4) * 16;
    const uint32_t bRow = (lane & 7) + ((lane >> 4) << 3);
    const uint32_t bCol = ((lane >> 3) & 1) * 16;

    const int fr0 = tid >> 2, fc0 = (tid & 3);
    const int fr1 = fr0 + 64;
    const uint32_t so0 = fr0 * (RS * 2) + fc0 * 16;
    const uint32_t so1 = fr1 * (RS * 2) + fc0 * 16;

    float acc[2][8][4];
#pragma unroll
    for (int f = 0; f < 2; f++)
#pragma unroll
        for (int j = 0; j < 8; j++)
#pragma unroll
            for (int e = 0; e < 4; e++) acc[f][j][e] = 0.f;

#define ISSUE_G(ck, st) do { \
    uint32_t o = (uint32_t)(st) * STG_A; \
    size_t kk = (size_t)(ck) * 32 + fc0 * 8; \
    size_t ga0 = (size_t)(m0 + fr0) * K + kk; \
    size_t ga1 = (size_t)(m0 + fr1) * K + kk; \
    size_t gb0 = (size_t)(n0 + fr0) * K + kk; \
    size_t gb1 = (size_t)(n0 + fr1) * K + kk; \
    cp16(uAh + o + so0, Ah + ga0); cp16(uAh + o + so1, Ah + ga1); \
    cp16(uBs + o + so0, Bs + gb0); cp16(uBs + o + so1, Bs + gb1); \
    CP_COMMIT(); \
} while (0)

    const int nck = K >> 5;
    ISSUE_G(0, 0);
    for (int ck = 0; ck < nck; ck++) {
        const int st = ck & 1;
        if (ck + 1 < nck) {
            ISSUE_G(ck + 1, (ck + 1) & 1);
            asm volatile("cp.async.wait_group 1;" ::: "memory");
        } else {
            asm volatile("cp.async.wait_group 0;" ::: "memory");
        }
        __syncthreads();

        const uint32_t oAh = uAh + st * STG_A;
        const uint32_t oBs = uBs + st * STG_A;
#pragma unroll
        for (int kh = 0; kh < 2; kh++) {
            const uint32_t kb = kh * 32;
            uint32_t ah[2][4];
            ldsm_x4(ah[0], oAh + (mb + aRow)      * (RS * 2) + kb + aCol);
            ldsm_x4(ah[1], oAh + (mb + 16 + aRow) * (RS * 2) + kb + aCol);
#pragma unroll
            for (int g = 0; g < 4; g++) {
                uint32_t bh[4];
                ldsm_x4(bh, oBs + (nb + g * 16 + bRow) * (RS * 2) + kb + bCol);
#pragma unroll
                for (int f = 0; f < 2; f++) {
#pragma unroll
                    for (int nn = 0; nn < 2; nn++) {
                        float* cc = acc[f][g * 2 + nn];
                        mma16816(cc, ah[f], bh[2 * nn], bh[2 * nn + 1]);
                    }
                }
            }
        }
        __syncthreads();
    }

    const int tg = lane >> 2, tig = lane & 3;
    __half* qtb = qtT ? qtT + (size_t)(m0 >> 10) * NP * SEQ : nullptr;
    double ls = 0.0, ls2 = 0.0;
#pragma unroll
    for (int f = 0; f < 2; f++) {
        int r0 = m0 + mb + f * 16 + tg;
        int rin = r0 & 1023;
        float* c0 = C ? C + (size_t)r0 * Nout : nullptr;
        float* c1 = C ? C + (size_t)(r0 + 8) * Nout : nullptr;
        const float* rr0 = resid ? resid + (size_t)r0 * Nout : nullptr;
        const float* rr1 = resid ? resid + (size_t)(r0 + 8) * Nout : nullptr;
        __half* sh0 = spH ? spH + (size_t)bz * sSp + (size_t)r0 * KP : nullptr;
        __half* sh1 = spH ? spH + (size_t)bz * sSp + (size_t)(r0 + 8) * KP : nullptr;
#pragma unroll
        for (int j = 0; j < 8; j++) {
            int cb = n0 + nb + j * 8 + tig * 2;
            float* a = acc[f][j];
#pragma unroll
            for (int e = 0; e < 2; e++) {
                int col = cb + e;
                if (col < Nout) {
                    float v0 = a[e] * alpha, v1 = a[e + 2] * alpha;
                    if (bias) { v0 += bias[col]; v1 += bias[col]; }
                    if (do_relu) { v0 = fmaxf(v0, 0.f); v1 = fmaxf(v1, 0.f); }
                    if (rr0) { v0 += rr0[col]; v1 += rr1[col]; }
                    if (c0) { c0[col] = v0; c1[col] = v1; }
                    __half h0 = __float2half(v0), h1 = __float2half(v1);
                    if (sh0) { sh0[col] = h0; sh1[col] = h1; }
                    if (qtb) {
                        qtb[(size_t)col * SEQ + rin]     = h0;
                        qtb[(size_t)col * SEQ + rin + 8] = h1;
                    }
                    if (LNACC) {
                        ls  += (double)v0 + (double)v1;
                        ls2 += (double)v0 * v0 + (double)v1 * v1;
                    }
                }
            }
        }
    }

    if (LNACC) {
#pragma unroll
        for (int o = 16; o; o >>= 1) {
            ls  += __shfl_xor_sync(0xffffffffu, ls,  o);
            ls2 += __shfl_xor_sync(0xffffffffu, ls2, o);
        }
        double* rp = (double*)dsm;     // stage buffers are dead now
        __syncthreads();
        if (lane == 0) { rp[wid] = ls; rp[8 + wid] = ls2; }
        __syncthreads();
        if (tid == 0) {
            double S = 0.0, S2 = 0.0;
#pragma unroll
            for (int i = 0; i < 8; i++) { S += rp[i]; S2 += rp[8 + i]; }
            int bb = m0 >> 10;
            atomicAdd(&g_psum[bb], S);
            atomicAdd(&g_psum2[bb], S2);
        }
    }
}

// ================= softmax: fp16 scores -> fp16 probabilities ===============
__global__ void __launch_bounds__(256) softmax_rows_k(const __half* __restrict__ S,
                                                      __half* __restrict__ Ph) {
    size_t row = blockIdx.x;
    const __half2* rp = (const __half2*)(S + row * SEQ);
    int t = threadIdx.x;
    __half2 a = rp[2 * t], b = rp[2 * t + 1];
    float4 v = make_float4(__low2float(a), __high2float(a),
                           __low2float(b), __high2float(b));
    float m = fmaxf(fmaxf(v.x, v.y), fmaxf(v.z, v.w));
#pragma unroll
    for (int o = 16; o; o >>= 1) m = fmaxf(m, __shfl_xor_sync(0xffffffffu, m, o));
    __shared__ float red[8], red2[8];
    if ((t & 31) == 0) red[t >> 5] = m;
    __syncthreads();
    m = red[0];
#pragma unroll
    for (int i = 1; i < 8; i++) m = fmaxf(m, red[i]);
    v.x = __expf(v.x - m); v.y = __expf(v.y - m);
    v.z = __expf(v.z - m); v.w = __expf(v.w - m);
    float s = v.x + v.y + v.z + v.w;
#pragma unroll
    for (int o = 16; o; o >>= 1) s += __shfl_xor_sync(0xffffffffu, s, o);
    if ((t & 31) == 0) red2[t >> 5] = s;
    __syncthreads();
    s = 0.f;
#pragma unroll
    for (int i = 0; i < 8; i++) s += red2[i];
    float inv = 1.0f / s;
    size_t o2 = (row * SEQ) / 2 + 2 * t;
    ((__half2*)Ph)[o2]     = __halves2half2(__float2half(v.x * inv), __float2half(v.y * inv));
    ((__half2*)Ph)[o2 + 1] = __halves2half2(__float2half(v.z * inv), __float2half(v.w * inv));
}

// ================= layernorm pass2 (stats precomputed by GEMM epilogue) =====
__global__ void __launch_bounds__(256) ln2_pass2(const float* __restrict__ y,
                                                 float* __restrict__ out,
                                                 __half* __restrict__ oh) {
    int b = blockIdx.x, ch = blockIdx.y;
    const double n = (double)NE;
    double mu = g_psum[b] / n;
    double var = g_psum2[b] / n - mu * mu;
    float muf = (float)mu;
    float inv = (float)(1.0 / sqrt(var + 1e-5));
    size_t base = (size_t)b * NE + (size_t)ch * CHUNK;
    for (int i = threadIdx.x; i < CHUNK; i += 256) {
        size_t e = base + i;
        float v = (y[e] - muf) * inv;
        out[e] = v;
        if (oh) {
            size_t r = e / EMB;
            int    k = (int)(e - r * EMB);
            oh[r * KP + k] = __float2half(v);
        }
    }
}

// ================= host orchestration =======================================
extern "C" void kernel_launch(void* const* d_in, const int* in_sizes, int n_in,
                              void* d_out, int out_size)
{
    const int*   x      = (const int*)  d_in[0];
    const float* embed  = (const float*)d_in[1];
    const float* w_qkv  = (const float*)d_in[2];
    const float* b_qkv  = (const float*)d_in[3];
    const float* w_fuse = (const float*)d_in[4];
    const float* b_fuse = (const float*)d_in[5];
    const float* w1     = (const float*)d_in[6];
    const float* b1     = (const float*)d_in[7];
    const float* w2     = (const float*)d_in[8];
    const float* b2     = (const float*)d_in[9];
    float*       out    = (float*)d_out;
    (void)in_sizes; (void)n_in; (void)out_size;

    cudaFuncSetAttribute(tgemm128_score, cudaFuncAttributeMaxDynamicSharedMemorySize, SM_TOT128);
    cudaFuncSetAttribute(tgemm128g<0>, cudaFuncAttributeMaxDynamicSharedMemorySize, SM_TOTG);
    cudaFuncSetAttribute(tgemm128g<1>, cudaFuncAttributeMaxDynamicSharedMemorySize, SM_TOTG);

    float *h, *y, *wfe;
    cudaGetSymbolAddress((void**)&h,   g_h);
    cudaGetSymbolAddress((void**)&y,   g_y);
    cudaGetSymbolAddress((void**)&wfe, g_wfe);
    __half *Sp,*Ahp,*Chp,*Qhp,*QTp,*Php,*Wq,*Wf,*W1,*W2;
    cudaGetSymbolAddress((void**)&Sp,  g_S);
    cudaGetSymbolAddress((void**)&Ahp, g_Ah);
    cudaGetSymbolAddress((void**)&Chp, g_Ch);
    cudaGetSymbolAddress((void**)&Qhp, g_Qh);
    cudaGetSymbolAddress((void**)&QTp, g_QT);
    cudaGetSymbolAddress((void**)&Php, g_Ph);
    cudaGetSymbolAddress((void**)&Wq,  g_Wq);  cudaGetSymbolAddress((void**)&Wf,  g_Wf);
    cudaGetSymbolAddress((void**)&W1,  g_W1);  cudaGetSymbolAddress((void**)&W2,  g_W2);

    const float inv_scale = 1.0f / sqrtf(200.0f);

    dim3 gFull(2, MROWS / 128, 1);       // N tiles of 128: ceil(200/128)=2
    dim3 gScoreSym(36, 1, BATCH);
    dim3 gCtx(2, SEQ / 128, BATCH);
    dim3 gLN(BATCH, LNCH);
    const size_t sQK = (size_t)SEQ * KP;
    const size_t sSS = (size_t)SEQ * SEQ;
    const size_t sQT = (size_t)NP * SEQ;

    // launch order keeps capture slot (4th launch) = tgemm128g<0> (q-proj)
    count_zeros_k<<<BATCH, 256>>>(x);                                   // 1
    embed_pos_k  <<<MROWS, 256>>>(x, embed);                            // 2
    wtsplit_k<<<(NP * KP) / 256, 256>>>(w_qkv, Wq);                     // 3

    for (int s = 0; s < NSTACK; s++) {
        // q = h @ w_qkv + b_qkv  -> fp16 Qh (row-major) + QT (transposed)
        tgemm128g<0><<<gFull, 256, SM_TOTG>>>(Ahp, Wq, nullptr, b_qkv, nullptr,
                                              Qhp, QTp, KP, EMB, 1.f, 0,
                                              0, 0, 0, 0);              // 4
        // S = fp16(q) fp16(q)^T / sqrt(D): symmetric, fp16 output
        tgemm128_score<<<gScoreSym, 256, SM_TOT128>>>(Qhp, Sp, KP, inv_scale, sQK, sSS);
        softmax_rows_k<<<MROWS, 256>>>(Sp, Php);
        if (s == 0) {
            build_wfe_k<<<(EMB * EMB + 255) / 256, 256>>>(w_fuse);
            wtsplit_k<<<(NP * KP) / 256, 256>>>(wfe, Wf);
            wtsplit_k<<<(NP * KP) / 256, 256>>>(w1,  W1);
            wtsplit_k<<<(NP * KP) / 256, 256>>>(w2,  W2);
        }
        // c = P @ q   (A = P fp16, B = q^T fp16; fp16 output only)
        tgemm128g<0><<<gCtx, 256, SM_TOTG>>>(Php, QTp, nullptr, nullptr, nullptr,
                                             Chp, nullptr, SEQ, EMB, 1.f, 0,
                                             sSS, sQT, 0, sQK);
        // y = c @ wfe + b_fuse + h   (+ fused LN stats)
        zero_ps_k<<<1, 32>>>();
        tgemm128g<1><<<gFull, 256, SM_TOTG>>>(Chp, Wf, y, b_fuse, h,
                                              nullptr, nullptr, KP, EMB, 1.f, 0,
                                              0, 0, 0, 0);
        ln2_pass2<<<gLN, 256>>>(y, h, Ahp);
        // ffn: t = relu(h@w1+b1) (fp16 out) ; y = t@w2+b2+h (+ LN stats)
        tgemm128g<0><<<gFull, 256, SM_TOTG>>>(Ahp, W1, nullptr, b1, nullptr,
                                              Chp, nullptr, KP, EMB, 1.f, 1,
                                              0, 0, 0, 0);
        zero_ps_k<<<1, 32>>>();
        tgemm128g<1><<<gFull, 256, SM_TOTG>>>(Chp, W2, y, b2, h,
                                              nullptr, nullptr, KP, EMB, 1.f, 0,
                                              0, 0, 0, 0);
        if (s == NSTACK - 1)
            ln2_pass2<<<gLN, 256>>>(y, out, nullptr);
        else
            ln2_pass2<<<gLN, 256>>>(y, h, Ahp);
    }
}